// round 12
// baseline (speedup 1.0000x reference)
#include <cuda_runtime.h>

#define NN 100000
#define CH 128
#define NE 1600000
#define OC 64
#define OUT_ELEMS (2LL * NN * OC)   // 12,800,000
#define HALF_OFF  (OUT_ELEMS / 2)   // 6,400,000
#define SCAN_BLK  391               // ceil(NN/256)

// Scratch (__device__ globals; NEVER passed as kernel args from host — GB300
// ATS makes the host-shadow silently valid-and-wrong).
__device__ float g_h0[(size_t)NN * CH];   // x@W1
__device__ float g_h1[(size_t)NN * CH];   // relu(gcn1)
__device__ float g_agg[(size_t)NN * CH];  // layer-2 aggregation
__device__ float g_dinv[NN];
__device__ float g_W2[CH * CH];           // [W_mu | W_ls]
__device__ float g_b2[CH];                // [b_mu | b_ls]
__device__ int   g_eidx[2 * NE];          // canonical int32 edge index
__device__ int   g_count[NN];             // in-degree histogram
__device__ int   g_rowstart[NN + 1];      // CSR row offsets
__device__ int   g_cursor[NN];            // fill cursors
__device__ int   g_csr_src[NE];           // CSR: src per edge, grouped by dst
__device__ int   g_partial[SCAN_BLK];     // scan partials
__device__ unsigned int g_orflag;

__global__ void crash_kernel() { *((volatile int*)0) = 1; }  // out_size mismatch signal

// ---------------- init: zero counts + orflag ----------------
__global__ void init_kernel() {
    long long stride = (long long)gridDim.x * blockDim.x;
    long long i0 = (long long)blockIdx.x * blockDim.x + threadIdx.x;
    if (i0 == 0) g_orflag = 0u;
    for (long long i = i0; i < NN; i += stride) g_count[i] = 0;
}

// ---------------- edge dtype detect ----------------
__global__ void detect_kernel(const unsigned int* __restrict__ ei32) {
    unsigned int acc = 0;
    long long stride = (long long)gridDim.x * blockDim.x;
    for (long long i = (long long)blockIdx.x * blockDim.x + threadIdx.x; i < NE; i += stride)
        acc |= ei32[2 * i + 1];
    #pragma unroll
    for (int o = 16; o > 0; o >>= 1) acc |= __shfl_down_sync(0xffffffffu, acc, o);
    if ((threadIdx.x & 31) == 0 && acc) atomicOr(&g_orflag, acc);
}

// ---------------- convert + fused dst histogram ----------------
__global__ void convert_hist_kernel(const void* __restrict__ ei) {
    long long stride = (long long)gridDim.x * blockDim.x;
    bool is64 = (g_orflag == 0u);
    for (long long i = (long long)blockIdx.x * blockDim.x + threadIdx.x; i < 2 * (long long)NE; i += stride) {
        int v = is64 ? (int)((const long long*)ei)[i] : ((const int*)ei)[i];
        g_eidx[i] = v;
        if (i >= NE && (unsigned)v < (unsigned)NN)   // dst half -> in-degree
            atomicAdd(&g_count[v], 1);
    }
}

// ---------------- dinv from counts ----------------
__global__ void dinv_kernel() {
    long long stride = (long long)gridDim.x * blockDim.x;
    for (long long i = (long long)blockIdx.x * blockDim.x + threadIdx.x; i < NN; i += stride)
        g_dinv[i] = rsqrtf((float)g_count[i] + 1.0f);
}

// ---------------- CSR build: block scan (3 stages) ----------------
__global__ void scan1_kernel() {
    __shared__ int sh[256];
    int b = blockIdx.x, t = threadIdx.x;
    int i = b * 256 + t;
    int c = (i < NN) ? g_count[i] : 0;
    sh[t] = c;
    __syncthreads();
    #pragma unroll
    for (int o = 1; o < 256; o <<= 1) {
        int v = (t >= o) ? sh[t - o] : 0;
        __syncthreads();
        sh[t] += v;
        __syncthreads();
    }
    if (i < NN) g_rowstart[i] = sh[t] - c;
    if (t == 255) g_partial[b] = sh[t];
}

__global__ void scan2_kernel() {
    if (threadIdx.x == 0 && blockIdx.x == 0) {
        int run = 0;
        for (int b = 0; b < SCAN_BLK; b++) {
            int v = g_partial[b];
            g_partial[b] = run;
            run += v;
        }
        g_rowstart[NN] = run;
    }
}

__global__ void scan3_kernel() {
    int b = blockIdx.x, t = threadIdx.x;
    int i = b * 256 + t;
    if (i < NN) {
        int rs = g_rowstart[i] + g_partial[b];
        g_rowstart[i] = rs;
        g_cursor[i] = rs;
    }
}

// ---------------- CSR fill ----------------
__global__ void fill_kernel() {
    long long stride = (long long)gridDim.x * blockDim.x;
    for (long long e = (long long)blockIdx.x * blockDim.x + threadIdx.x; e < NE; e += stride) {
        int s = g_eidx[e];
        int d = g_eidx[NE + e];
        if ((unsigned)s >= (unsigned)NN || (unsigned)d >= (unsigned)NN) continue;
        int pos = atomicAdd(&g_cursor[d], 1);
        g_csr_src[pos] = s;
    }
}

// ---------------- pull aggregation: warp per node, software-pipelined ----------------
// agg[d] = dinv[d] * Sum_{s in in(d)} dinv[s]*H[s]  +  dinv[d]^2 * H[d]
// LAYER==1: += b1, relu, write g_h1 (reads g_h0).
// LAYER==2: write g_agg raw (reads g_h1); bias added in gemm_l2.
template <int LAYER>
__global__ void pull_kernel(const float* __restrict__ b1) {
    long long gt = (long long)blockIdx.x * blockDim.x + threadIdx.x;
    int n = (int)(gt >> 5);
    int lane = (int)(gt & 31);
    if (n >= NN) return;
    const float* H = (LAYER == 1) ? g_h0 : g_h1;
    int row = g_rowstart[n];
    int end = g_rowstart[n + 1];
    float4 acc = make_float4(0.f, 0.f, 0.f, 0.f);
    // software pipeline: prefetch next src index + weight one iteration ahead
    int s_next = (row < end) ? g_csr_src[row] : 0;
    float w_next = (row < end) ? g_dinv[s_next] : 0.f;
    for (int e = row; e < end; e++) {
        int s = s_next;
        float ws = w_next;
        if (e + 1 < end) {
            s_next = g_csr_src[e + 1];
            w_next = g_dinv[s_next];
        }
        float4 v = ((const float4*)(H + (size_t)s * CH))[lane];
        acc.x = fmaf(ws, v.x, acc.x);
        acc.y = fmaf(ws, v.y, acc.y);
        acc.z = fmaf(ws, v.z, acc.z);
        acc.w = fmaf(ws, v.w, acc.w);
    }
    float dd = g_dinv[n];
    float4 hd = ((const float4*)(H + (size_t)n * CH))[lane];
    float4 r;
    r.x = dd * acc.x + dd * dd * hd.x;
    r.y = dd * acc.y + dd * dd * hd.y;
    r.z = dd * acc.z + dd * dd * hd.z;
    r.w = dd * acc.w + dd * dd * hd.w;
    if (LAYER == 1) {
        float4 b = ((const float4*)b1)[lane];
        r.x = fmaxf(r.x + b.x, 0.f);
        r.y = fmaxf(r.y + b.y, 0.f);
        r.z = fmaxf(r.z + b.z, 0.f);
        r.w = fmaxf(r.w + b.w, 0.f);
        ((float4*)(g_h1 + (size_t)n * CH))[lane] = r;
    } else {
        ((float4*)(g_agg + (size_t)n * CH))[lane] = r;
    }
}

// ---------------- pack [W_mu|W_ls], [b_mu|b_ls] ----------------
__global__ void pack_kernel(const float* __restrict__ Wmu, const float* __restrict__ Wls,
                            const float* __restrict__ bmu, const float* __restrict__ bls) {
    int i = blockIdx.x * blockDim.x + threadIdx.x;
    if (i < CH * OC) {
        int r = i / OC, c = i % OC;
        g_W2[r * CH + c]      = Wmu[i];
        g_W2[r * CH + OC + c] = Wls[i];
    }
    if (i < OC) {
        g_b2[i]      = bmu[i];
        g_b2[OC + i] = bls[i];
    }
}

// ---------------- register-tiled SGEMM (128x128 tile, BK=8, 8x8 micro) ----------------
template <int MODE>
__device__ __forceinline__ void sgemm_core(const float* __restrict__ A,
                                           const float* __restrict__ Bsrc,
                                           float* __restrict__ Cout) {
    __shared__ float As[8][128];
    __shared__ float Bs[8][128];
    int tid = threadIdx.x;
    int tr = tid >> 4;
    int tc = tid & 15;
    long long rowBase = (long long)blockIdx.x * 128;

    float acc[8][8];
#pragma unroll
    for (int i = 0; i < 8; i++)
#pragma unroll
        for (int j = 0; j < 8; j++) acc[i][j] = 0.f;

    int arow = tid >> 1;
    int acol = (tid & 1) * 4;
    int brow = tid >> 5;
    int bcol = (tid & 31) * 4;
    long long gr0 = rowBase + arow;

    for (int kt = 0; kt < 128; kt += 8) {
        float4 av = make_float4(0.f, 0.f, 0.f, 0.f);
        if (gr0 < NN) av = *(const float4*)(A + (size_t)gr0 * 128 + kt + acol);
        As[acol + 0][arow] = av.x;
        As[acol + 1][arow] = av.y;
        As[acol + 2][arow] = av.z;
        As[acol + 3][arow] = av.w;
        float4 bv = *(const float4*)(Bsrc + (size_t)(kt + brow) * 128 + bcol);
        *(float4*)&Bs[brow][bcol] = bv;
        __syncthreads();
#pragma unroll
        for (int k = 0; k < 8; k++) {
            float a[8], b[8];
#pragma unroll
            for (int i = 0; i < 8; i++) a[i] = As[k][tr * 8 + i];
#pragma unroll
            for (int j = 0; j < 8; j++) b[j] = Bs[k][tc * 8 + j];
#pragma unroll
            for (int i = 0; i < 8; i++)
#pragma unroll
                for (int j = 0; j < 8; j++) acc[i][j] = fmaf(a[i], b[j], acc[i][j]);
        }
        __syncthreads();
    }

#pragma unroll
    for (int i = 0; i < 8; i++) {
        long long r = rowBase + tr * 8 + i;
        if (r >= NN) continue;
        if (MODE == 0) {
            float* cp = g_h0 + (size_t)r * 128 + tc * 8;
            *(float4*)(cp + 0) = make_float4(acc[i][0], acc[i][1], acc[i][2], acc[i][3]);
            *(float4*)(cp + 4) = make_float4(acc[i][4], acc[i][5], acc[i][6], acc[i][7]);
        } else {
            int c0 = tc * 8;
            float vb[8];
#pragma unroll
            for (int j = 0; j < 8; j++) vb[j] = acc[i][j] + g_b2[c0 + j];
            float* base;
            int cc;
            if (c0 < OC) { base = Cout;            cc = c0; }
            else         { base = Cout + HALF_OFF; cc = c0 - OC; }
            float* cp = base + (size_t)r * OC + cc;
            *(float4*)(cp + 0) = make_float4(vb[0], vb[1], vb[2], vb[3]);
            *(float4*)(cp + 4) = make_float4(vb[4], vb[5], vb[6], vb[7]);
        }
    }
}

__global__ void gemm_l1_kernel(const float* __restrict__ A, const float* __restrict__ B) {
    sgemm_core<0>(A, B, nullptr);        // g_h0 = x @ W1
}
__global__ void gemm_l2_kernel(float* __restrict__ Cout) {
    sgemm_core<1>(g_agg, g_W2, Cout);    // out = g_agg @ g_W2 + g_b2 (split)
}

// ---------------- launch ----------------
extern "C" void kernel_launch(void* const* d_in, const int* in_sizes, int n_in,
                              void* d_out, int out_size) {
    const float *x = 0, *W1 = 0, *b1 = 0, *Wmu = 0, *Wls = 0, *bmu = 0, *bls = 0;
    const void *ei = 0;
    for (int i = 0; i < n_in; i++) {
        long long s = in_sizes[i];
        if (s == 12800000LL)                        x  = (const float*)d_in[i];
        else if (s == 3200000LL || s == 6400000LL)  ei = d_in[i];
        else if (s == 16384LL)                      W1 = (const float*)d_in[i];
        else if (s == 128LL)                        b1 = (const float*)d_in[i];
        else if (s == 8192LL) { if (!Wmu) Wmu = (const float*)d_in[i]; else Wls = (const float*)d_in[i]; }
        else if (s == 64LL)   { if (!bmu) bmu = (const float*)d_in[i]; else bls = (const float*)d_in[i]; }
    }
    float* out = (float*)d_out;
    if (!x || !ei || !W1 || !b1 || !Wmu || !Wls || !bmu || !bls) return;  // Signal A
    if (!((long long)out_size == OUT_ELEMS || (long long)out_size == 4 * OUT_ELEMS)) {
        crash_kernel<<<1, 1>>>();  // Signal B
        return;
    }

    const int T = 256;
    int gemmBlocks = (NN + 127) / 128;       // 782
    int pullBlocks = (NN * 32 + T - 1) / T;  // 12500

    // Fork a side stream for the GEMM-l1/pack branch (independent of edges).
    // kernel_launch only runs for the eager correctness call + one capture call,
    // so leaking these (cannot destroy a stream mid-capture) is bounded and safe.
    cudaStream_t s1;
    cudaEvent_t evFork, evJoin;
    cudaStreamCreateWithFlags(&s1, cudaStreamNonBlocking);
    cudaEventCreateWithFlags(&evFork, cudaEventDisableTiming);
    cudaEventCreateWithFlags(&evJoin, cudaEventDisableTiming);

    // head (stream 0)
    init_kernel<<<400, T>>>();
    detect_kernel<<<256, T>>>((const unsigned int*)ei);

    // fork: branch B on s1 = gemm_l1 + pack (needs nothing from edge pipeline)
    cudaEventRecord(evFork, 0);
    cudaStreamWaitEvent(s1, evFork, 0);
    gemm_l1_kernel<<<gemmBlocks, T, 0, s1>>>(x, W1);
    pack_kernel<<<(CH * OC + T - 1) / T, T, 0, s1>>>(Wmu, Wls, bmu, bls);
    cudaEventRecord(evJoin, s1);

    // branch A (stream 0): edge pipeline -> CSR
    convert_hist_kernel<<<4096, T>>>(ei);
    dinv_kernel<<<400, T>>>();
    scan1_kernel<<<SCAN_BLK, T>>>();
    scan2_kernel<<<1, 32>>>();
    scan3_kernel<<<SCAN_BLK, T>>>();
    fill_kernel<<<4096, T>>>();

    // join: pulls + final GEMM need both branches
    cudaStreamWaitEvent(0, evJoin, 0);
    pull_kernel<1><<<pullBlocks, T>>>(b1);
    pull_kernel<2><<<pullBlocks, T>>>(nullptr);
    gemm_l2_kernel<<<gemmBlocks, T>>>(out);
}

// round 13
// speedup vs baseline: 1.1741x; 1.1741x over previous
#include <cuda_runtime.h>
#include <cuda_fp16.h>

#define NN 100000
#define CH 128
#define NE 1600000
#define OC 64
#define OUT_ELEMS (2LL * NN * OC)   // 12,800,000
#define HALF_OFF  (OUT_ELEMS / 2)   // 6,400,000
#define SCAN_BLK  391               // ceil(NN/256)

// Scratch (__device__ globals; NEVER passed as kernel args from host — GB300
// ATS makes the host-shadow silently valid-and-wrong).
__device__ __half g_h0h[(size_t)NN * CH]; // x@W1, fp16 (gather payload)
__device__ __half g_h1h[(size_t)NN * CH]; // relu(gcn1), fp16 (gather payload)
__device__ float g_agg[(size_t)NN * CH];  // layer-2 aggregation (fp32 for GEMM)
__device__ float g_dinv[NN];
__device__ float g_W2[CH * CH];           // [W_mu | W_ls]
__device__ float g_b2[CH];                // [b_mu | b_ls]
__device__ int   g_eidx[2 * NE];          // canonical int32 edge index
__device__ int   g_count[NN];             // in-degree histogram
__device__ int   g_rowstart[NN + 1];      // CSR row offsets
__device__ int   g_cursor[NN];            // fill cursors
__device__ int   g_csr_src[NE];           // CSR: src per edge, grouped by dst
__device__ int   g_partial[SCAN_BLK];     // scan partials
__device__ unsigned int g_orflag;

__global__ void crash_kernel() { *((volatile int*)0) = 1; }  // out_size mismatch signal

// ---------------- init: zero counts + orflag ----------------
__global__ void init_kernel() {
    long long stride = (long long)gridDim.x * blockDim.x;
    long long i0 = (long long)blockIdx.x * blockDim.x + threadIdx.x;
    if (i0 == 0) g_orflag = 0u;
    for (long long i = i0; i < NN; i += stride) g_count[i] = 0;
}

// ---------------- edge dtype detect ----------------
__global__ void detect_kernel(const unsigned int* __restrict__ ei32) {
    unsigned int acc = 0;
    long long stride = (long long)gridDim.x * blockDim.x;
    for (long long i = (long long)blockIdx.x * blockDim.x + threadIdx.x; i < NE; i += stride)
        acc |= ei32[2 * i + 1];
    #pragma unroll
    for (int o = 16; o > 0; o >>= 1) acc |= __shfl_down_sync(0xffffffffu, acc, o);
    if ((threadIdx.x & 31) == 0 && acc) atomicOr(&g_orflag, acc);
}

// ---------------- convert + fused dst histogram ----------------
__global__ void convert_hist_kernel(const void* __restrict__ ei) {
    long long stride = (long long)gridDim.x * blockDim.x;
    bool is64 = (g_orflag == 0u);
    for (long long i = (long long)blockIdx.x * blockDim.x + threadIdx.x; i < 2 * (long long)NE; i += stride) {
        int v = is64 ? (int)((const long long*)ei)[i] : ((const int*)ei)[i];
        g_eidx[i] = v;
        if (i >= NE && (unsigned)v < (unsigned)NN)   // dst half -> in-degree
            atomicAdd(&g_count[v], 1);
    }
}

// ---------------- dinv from counts ----------------
__global__ void dinv_kernel() {
    long long stride = (long long)gridDim.x * blockDim.x;
    for (long long i = (long long)blockIdx.x * blockDim.x + threadIdx.x; i < NN; i += stride)
        g_dinv[i] = rsqrtf((float)g_count[i] + 1.0f);
}

// ---------------- CSR build: block scan (3 stages) ----------------
__global__ void scan1_kernel() {
    __shared__ int sh[256];
    int b = blockIdx.x, t = threadIdx.x;
    int i = b * 256 + t;
    int c = (i < NN) ? g_count[i] : 0;
    sh[t] = c;
    __syncthreads();
    #pragma unroll
    for (int o = 1; o < 256; o <<= 1) {
        int v = (t >= o) ? sh[t - o] : 0;
        __syncthreads();
        sh[t] += v;
        __syncthreads();
    }
    if (i < NN) g_rowstart[i] = sh[t] - c;
    if (t == 255) g_partial[b] = sh[t];
}

__global__ void scan2_kernel() {
    if (threadIdx.x == 0 && blockIdx.x == 0) {
        int run = 0;
        for (int b = 0; b < SCAN_BLK; b++) {
            int v = g_partial[b];
            g_partial[b] = run;
            run += v;
        }
        g_rowstart[NN] = run;
    }
}

__global__ void scan3_kernel() {
    int b = blockIdx.x, t = threadIdx.x;
    int i = b * 256 + t;
    if (i < NN) {
        int rs = g_rowstart[i] + g_partial[b];
        g_rowstart[i] = rs;
        g_cursor[i] = rs;
    }
}

// ---------------- CSR fill ----------------
__global__ void fill_kernel() {
    long long stride = (long long)gridDim.x * blockDim.x;
    for (long long e = (long long)blockIdx.x * blockDim.x + threadIdx.x; e < NE; e += stride) {
        int s = g_eidx[e];
        int d = g_eidx[NE + e];
        if ((unsigned)s >= (unsigned)NN || (unsigned)d >= (unsigned)NN) continue;
        int pos = atomicAdd(&g_cursor[d], 1);
        g_csr_src[pos] = s;
    }
}

// ---------------- pull aggregation: warp per node, fp16 gather ----------------
// agg[d] = dinv[d] * Sum_{s in in(d)} dinv[s]*H[s]  +  dinv[d]^2 * H[d]
// LAYER==1: += b1, relu, write g_h1h (reads g_h0h).
// LAYER==2: write g_agg fp32 (reads g_h1h); bias added in gemm_l2.
template <int LAYER>
__global__ void pull_kernel(const float* __restrict__ b1) {
    long long gt = (long long)blockIdx.x * blockDim.x + threadIdx.x;
    int n = (int)(gt >> 5);
    int lane = (int)(gt & 31);
    if (n >= NN) return;
    const __half* H = (LAYER == 1) ? g_h0h : g_h1h;
    int row = g_rowstart[n];
    int end = g_rowstart[n + 1];
    float4 acc = make_float4(0.f, 0.f, 0.f, 0.f);
    #pragma unroll 2
    for (int e = row; e < end; e++) {
        int s = g_csr_src[e];                     // broadcast load
        float ws = g_dinv[s];                     // broadcast load
        uint2 raw = *(const uint2*)(H + (size_t)s * CH + lane * 4);   // 4 halves
        float2 f0 = __half22float2(*reinterpret_cast<__half2*>(&raw.x));
        float2 f1 = __half22float2(*reinterpret_cast<__half2*>(&raw.y));
        acc.x = fmaf(ws, f0.x, acc.x);
        acc.y = fmaf(ws, f0.y, acc.y);
        acc.z = fmaf(ws, f1.x, acc.z);
        acc.w = fmaf(ws, f1.y, acc.w);
    }
    float dd = g_dinv[n];
    uint2 rawd = *(const uint2*)(H + (size_t)n * CH + lane * 4);
    float2 h0 = __half22float2(*reinterpret_cast<__half2*>(&rawd.x));
    float2 h1 = __half22float2(*reinterpret_cast<__half2*>(&rawd.y));
    float4 r;
    r.x = dd * acc.x + dd * dd * h0.x;
    r.y = dd * acc.y + dd * dd * h0.y;
    r.z = dd * acc.z + dd * dd * h1.x;
    r.w = dd * acc.w + dd * dd * h1.y;
    if (LAYER == 1) {
        float4 b = ((const float4*)b1)[lane];
        r.x = fmaxf(r.x + b.x, 0.f);
        r.y = fmaxf(r.y + b.y, 0.f);
        r.z = fmaxf(r.z + b.z, 0.f);
        r.w = fmaxf(r.w + b.w, 0.f);
        uint2 outp;
        *reinterpret_cast<__half2*>(&outp.x) = __floats2half2_rn(r.x, r.y);
        *reinterpret_cast<__half2*>(&outp.y) = __floats2half2_rn(r.z, r.w);
        *(uint2*)(g_h1h + (size_t)n * CH + lane * 4) = outp;
    } else {
        ((float4*)(g_agg + (size_t)n * CH))[lane] = r;
    }
}

// ---------------- pack [W_mu|W_ls], [b_mu|b_ls] ----------------
__global__ void pack_kernel(const float* __restrict__ Wmu, const float* __restrict__ Wls,
                            const float* __restrict__ bmu, const float* __restrict__ bls) {
    int i = blockIdx.x * blockDim.x + threadIdx.x;
    if (i < CH * OC) {
        int r = i / OC, c = i % OC;
        g_W2[r * CH + c]      = Wmu[i];
        g_W2[r * CH + OC + c] = Wls[i];
    }
    if (i < OC) {
        g_b2[i]      = bmu[i];
        g_b2[OC + i] = bls[i];
    }
}

// ---------------- register-tiled SGEMM (128x128 tile, BK=8, 8x8 micro) ----------------
// MODE 0: write g_h0h as fp16 (device symbol). MODE 1: bias + split write to out.
template <int MODE>
__device__ __forceinline__ void sgemm_core(const float* __restrict__ A,
                                           const float* __restrict__ Bsrc,
                                           float* __restrict__ Cout) {
    __shared__ float As[8][128];
    __shared__ float Bs[8][128];
    int tid = threadIdx.x;
    int tr = tid >> 4;
    int tc = tid & 15;
    long long rowBase = (long long)blockIdx.x * 128;

    float acc[8][8];
#pragma unroll
    for (int i = 0; i < 8; i++)
#pragma unroll
        for (int j = 0; j < 8; j++) acc[i][j] = 0.f;

    int arow = tid >> 1;
    int acol = (tid & 1) * 4;
    int brow = tid >> 5;
    int bcol = (tid & 31) * 4;
    long long gr0 = rowBase + arow;

    for (int kt = 0; kt < 128; kt += 8) {
        float4 av = make_float4(0.f, 0.f, 0.f, 0.f);
        if (gr0 < NN) av = *(const float4*)(A + (size_t)gr0 * 128 + kt + acol);
        As[acol + 0][arow] = av.x;
        As[acol + 1][arow] = av.y;
        As[acol + 2][arow] = av.z;
        As[acol + 3][arow] = av.w;
        float4 bv = *(const float4*)(Bsrc + (size_t)(kt + brow) * 128 + bcol);
        *(float4*)&Bs[brow][bcol] = bv;
        __syncthreads();
#pragma unroll
        for (int k = 0; k < 8; k++) {
            float a[8], b[8];
#pragma unroll
            for (int i = 0; i < 8; i++) a[i] = As[k][tr * 8 + i];
#pragma unroll
            for (int j = 0; j < 8; j++) b[j] = Bs[k][tc * 8 + j];
#pragma unroll
            for (int i = 0; i < 8; i++)
#pragma unroll
                for (int j = 0; j < 8; j++) acc[i][j] = fmaf(a[i], b[j], acc[i][j]);
        }
        __syncthreads();
    }

#pragma unroll
    for (int i = 0; i < 8; i++) {
        long long r = rowBase + tr * 8 + i;
        if (r >= NN) continue;
        if (MODE == 0) {
            // write 8 fp16 channels (16 bytes, aligned)
            int c0 = tc * 8;
            __half2 hv[4];
#pragma unroll
            for (int j = 0; j < 4; j++)
                hv[j] = __floats2half2_rn(acc[i][2 * j], acc[i][2 * j + 1]);
            *(uint4*)(g_h0h + (size_t)r * CH + c0) = *reinterpret_cast<uint4*>(hv);
        } else {
            int c0 = tc * 8;
            float vb[8];
#pragma unroll
            for (int j = 0; j < 8; j++) vb[j] = acc[i][j] + g_b2[c0 + j];
            float* base;
            int cc;
            if (c0 < OC) { base = Cout;            cc = c0; }
            else         { base = Cout + HALF_OFF; cc = c0 - OC; }
            float* cp = base + (size_t)r * OC + cc;
            *(float4*)(cp + 0) = make_float4(vb[0], vb[1], vb[2], vb[3]);
            *(float4*)(cp + 4) = make_float4(vb[4], vb[5], vb[6], vb[7]);
        }
    }
}

__global__ void gemm_l1_kernel(const float* __restrict__ A, const float* __restrict__ B) {
    sgemm_core<0>(A, B, nullptr);        // g_h0h = fp16(x @ W1)
}
__global__ void gemm_l2_kernel(float* __restrict__ Cout) {
    sgemm_core<1>(g_agg, g_W2, Cout);    // out = g_agg @ g_W2 + g_b2 (split)
}

// ---------------- launch ----------------
extern "C" void kernel_launch(void* const* d_in, const int* in_sizes, int n_in,
                              void* d_out, int out_size) {
    const float *x = 0, *W1 = 0, *b1 = 0, *Wmu = 0, *Wls = 0, *bmu = 0, *bls = 0;
    const void *ei = 0;
    for (int i = 0; i < n_in; i++) {
        long long s = in_sizes[i];
        if (s == 12800000LL)                        x  = (const float*)d_in[i];
        else if (s == 3200000LL || s == 6400000LL)  ei = d_in[i];
        else if (s == 16384LL)                      W1 = (const float*)d_in[i];
        else if (s == 128LL)                        b1 = (const float*)d_in[i];
        else if (s == 8192LL) { if (!Wmu) Wmu = (const float*)d_in[i]; else Wls = (const float*)d_in[i]; }
        else if (s == 64LL)   { if (!bmu) bmu = (const float*)d_in[i]; else bls = (const float*)d_in[i]; }
    }
    float* out = (float*)d_out;
    if (!x || !ei || !W1 || !b1 || !Wmu || !Wls || !bmu || !bls) return;  // Signal A
    if (!((long long)out_size == OUT_ELEMS || (long long)out_size == 4 * OUT_ELEMS)) {
        crash_kernel<<<1, 1>>>();  // Signal B
        return;
    }

    const int T = 256;
    int gemmBlocks = (NN + 127) / 128;       // 782
    int pullBlocks = (NN * 32 + T - 1) / T;  // 12500

    // canonicalize edges + degree histogram (single stream — R12 fork/join regressed)
    init_kernel<<<400, T>>>();
    detect_kernel<<<256, T>>>((const unsigned int*)ei);
    convert_hist_kernel<<<4096, T>>>(ei);
    dinv_kernel<<<400, T>>>();

    // CSR build (by dst)
    scan1_kernel<<<SCAN_BLK, T>>>();
    scan2_kernel<<<1, 32>>>();
    scan3_kernel<<<SCAN_BLK, T>>>();
    fill_kernel<<<4096, T>>>();

    // layer 1: g_h0h = fp16(x @ W1) ; g_h1h = fp16(relu(pull(g_h0h) + b1))
    gemm_l1_kernel<<<gemmBlocks, T>>>(x, W1);
    pull_kernel<1><<<pullBlocks, T>>>(b1);

    // layer 2: g_agg = pull(g_h1h) ; out = g_agg @ [W_mu|W_ls] + [b_mu|b_ls]
    pull_kernel<2><<<pullBlocks, T>>>(nullptr);
    pack_kernel<<<(CH * OC + T - 1) / T, T>>>(Wmu, Wls, bmu, bls);
    gemm_l2_kernel<<<gemmBlocks, T>>>(out);
}

// round 14
// speedup vs baseline: 1.4947x; 1.2730x over previous
#include <cuda_runtime.h>
#include <cuda_fp16.h>

#define NN 100000
#define CH 128
#define NE 1600000
#define OC 64
#define OUT_ELEMS (2LL * NN * OC)   // 12,800,000
#define HALF_OFF  (OUT_ELEMS / 2)   // 6,400,000
#define SCAN_BLK  391               // ceil(NN/256)
#define SPAD 136                    // padded K-stride in halves (conflict-free)

// Scratch (__device__ globals; NEVER passed as kernel args from host — GB300
// ATS makes the host-shadow silently valid-and-wrong).
__device__ __half g_h0h[(size_t)NN * CH]; // fp16(x@W1)
__device__ __half g_h1h[(size_t)NN * CH]; // fp16(relu(gcn1))
__device__ __half g_aggh[(size_t)NN * CH];// fp16(layer-2 aggregation)
__device__ float g_dinv[NN];
__device__ __half g_W2h[CH * CH];         // fp16 [W_mu | W_ls], row-major [k][n]
__device__ float g_b2[CH];                // [b_mu | b_ls]
__device__ int   g_eidx[2 * NE];          // canonical int32 edge index
__device__ int   g_count[NN];             // in-degree histogram
__device__ int   g_rowstart[NN + 1];      // CSR row offsets
__device__ int   g_cursor[NN];            // fill cursors
__device__ int   g_csr_src[NE];           // CSR: src per edge, grouped by dst
__device__ int   g_partial[SCAN_BLK];
__device__ unsigned int g_orflag;

__global__ void crash_kernel() { *((volatile int*)0) = 1; }  // out_size mismatch signal

// ---------------- init ----------------
__global__ void init_kernel() {
    long long stride = (long long)gridDim.x * blockDim.x;
    long long i0 = (long long)blockIdx.x * blockDim.x + threadIdx.x;
    if (i0 == 0) g_orflag = 0u;
    for (long long i = i0; i < NN; i += stride) g_count[i] = 0;
}

// ---------------- edge dtype detect ----------------
__global__ void detect_kernel(const unsigned int* __restrict__ ei32) {
    unsigned int acc = 0;
    long long stride = (long long)gridDim.x * blockDim.x;
    for (long long i = (long long)blockIdx.x * blockDim.x + threadIdx.x; i < NE; i += stride)
        acc |= ei32[2 * i + 1];
    #pragma unroll
    for (int o = 16; o > 0; o >>= 1) acc |= __shfl_down_sync(0xffffffffu, acc, o);
    if ((threadIdx.x & 31) == 0 && acc) atomicOr(&g_orflag, acc);
}

// ---------------- convert + fused dst histogram ----------------
__global__ void convert_hist_kernel(const void* __restrict__ ei) {
    long long stride = (long long)gridDim.x * blockDim.x;
    bool is64 = (g_orflag == 0u);
    for (long long i = (long long)blockIdx.x * blockDim.x + threadIdx.x; i < 2 * (long long)NE; i += stride) {
        int v = is64 ? (int)((const long long*)ei)[i] : ((const int*)ei)[i];
        g_eidx[i] = v;
        if (i >= NE && (unsigned)v < (unsigned)NN)
            atomicAdd(&g_count[v], 1);
    }
}

__global__ void dinv_kernel() {
    long long stride = (long long)gridDim.x * blockDim.x;
    for (long long i = (long long)blockIdx.x * blockDim.x + threadIdx.x; i < NN; i += stride)
        g_dinv[i] = rsqrtf((float)g_count[i] + 1.0f);
}

// ---------------- CSR build: scan + fill ----------------
__global__ void scan1_kernel() {
    __shared__ int sh[256];
    int b = blockIdx.x, t = threadIdx.x;
    int i = b * 256 + t;
    int c = (i < NN) ? g_count[i] : 0;
    sh[t] = c;
    __syncthreads();
    #pragma unroll
    for (int o = 1; o < 256; o <<= 1) {
        int v = (t >= o) ? sh[t - o] : 0;
        __syncthreads();
        sh[t] += v;
        __syncthreads();
    }
    if (i < NN) g_rowstart[i] = sh[t] - c;
    if (t == 255) g_partial[b] = sh[t];
}

__global__ void scan2_kernel() {
    if (threadIdx.x == 0 && blockIdx.x == 0) {
        int run = 0;
        for (int b = 0; b < SCAN_BLK; b++) {
            int v = g_partial[b];
            g_partial[b] = run;
            run += v;
        }
        g_rowstart[NN] = run;
    }
}

__global__ void scan3_kernel() {
    int b = blockIdx.x, t = threadIdx.x;
    int i = b * 256 + t;
    if (i < NN) {
        int rs = g_rowstart[i] + g_partial[b];
        g_rowstart[i] = rs;
        g_cursor[i] = rs;
    }
}

__global__ void fill_kernel() {
    long long stride = (long long)gridDim.x * blockDim.x;
    for (long long e = (long long)blockIdx.x * blockDim.x + threadIdx.x; e < NE; e += stride) {
        int s = g_eidx[e];
        int d = g_eidx[NE + e];
        if ((unsigned)s >= (unsigned)NN || (unsigned)d >= (unsigned)NN) continue;
        int pos = atomicAdd(&g_cursor[d], 1);
        g_csr_src[pos] = s;
    }
}

// ---------------- pull aggregation: warp per node, fp16 gather ----------------
// LAYER==1: reads g_h0h, writes g_h1h = fp16(relu(... + b1)).
// LAYER==2: reads g_h1h, writes g_aggh = fp16(...).
template <int LAYER>
__global__ void pull_kernel(const float* __restrict__ b1) {
    long long gt = (long long)blockIdx.x * blockDim.x + threadIdx.x;
    int n = (int)(gt >> 5);
    int lane = (int)(gt & 31);
    if (n >= NN) return;
    const __half* H = (LAYER == 1) ? g_h0h : g_h1h;
    int row = g_rowstart[n];
    int end = g_rowstart[n + 1];
    float4 acc = make_float4(0.f, 0.f, 0.f, 0.f);
    #pragma unroll 2
    for (int e = row; e < end; e++) {
        int s = g_csr_src[e];
        float ws = g_dinv[s];
        uint2 raw = *(const uint2*)(H + (size_t)s * CH + lane * 4);
        float2 f0 = __half22float2(*reinterpret_cast<__half2*>(&raw.x));
        float2 f1 = __half22float2(*reinterpret_cast<__half2*>(&raw.y));
        acc.x = fmaf(ws, f0.x, acc.x);
        acc.y = fmaf(ws, f0.y, acc.y);
        acc.z = fmaf(ws, f1.x, acc.z);
        acc.w = fmaf(ws, f1.y, acc.w);
    }
    float dd = g_dinv[n];
    uint2 rawd = *(const uint2*)(H + (size_t)n * CH + lane * 4);
    float2 h0 = __half22float2(*reinterpret_cast<__half2*>(&rawd.x));
    float2 h1 = __half22float2(*reinterpret_cast<__half2*>(&rawd.y));
    float4 r;
    r.x = dd * acc.x + dd * dd * h0.x;
    r.y = dd * acc.y + dd * dd * h0.y;
    r.z = dd * acc.z + dd * dd * h1.x;
    r.w = dd * acc.w + dd * dd * h1.y;
    uint2 outp;
    if (LAYER == 1) {
        float4 b = ((const float4*)b1)[lane];
        r.x = fmaxf(r.x + b.x, 0.f);
        r.y = fmaxf(r.y + b.y, 0.f);
        r.z = fmaxf(r.z + b.z, 0.f);
        r.w = fmaxf(r.w + b.w, 0.f);
        *reinterpret_cast<__half2*>(&outp.x) = __floats2half2_rn(r.x, r.y);
        *reinterpret_cast<__half2*>(&outp.y) = __floats2half2_rn(r.z, r.w);
        *(uint2*)(g_h1h + (size_t)n * CH + lane * 4) = outp;
    } else {
        *reinterpret_cast<__half2*>(&outp.x) = __floats2half2_rn(r.x, r.y);
        *reinterpret_cast<__half2*>(&outp.y) = __floats2half2_rn(r.z, r.w);
        *(uint2*)(g_aggh + (size_t)n * CH + lane * 4) = outp;
    }
}

// ---------------- pack [W_mu|W_ls] -> fp16 g_W2h, [b_mu|b_ls] -> g_b2 ----------------
__global__ void pack_kernel(const float* __restrict__ Wmu, const float* __restrict__ Wls,
                            const float* __restrict__ bmu, const float* __restrict__ bls) {
    int i = blockIdx.x * blockDim.x + threadIdx.x;
    if (i < CH * OC) {
        int r = i / OC, c = i % OC;
        g_W2h[r * CH + c]      = __float2half_rn(Wmu[i]);
        g_W2h[r * CH + OC + c] = __float2half_rn(Wls[i]);
    }
    if (i < OC) {
        g_b2[i]      = bmu[i];
        g_b2[OC + i] = bls[i];
    }
}

// ---------------- HMMA GEMM: C[M x 128] = A[M x 128] @ B[128 x 128] ----------------
// mma.sync.m16n8k16 f16*f16->f32. Block 256 thr (8 warps), tile 128 rows.
// K=128 staged fully in smem: As[128][SPAD] halves, Bt[n][SPAD] halves (n-major).
// MODE 0: A = x (fp32 arg), B = W1 (fp32 arg), out -> g_h0h fp16.
// MODE 1: A = g_aggh (fp16 symbol), B = g_W2h (fp16 symbol), out -> bias+split fp32.
template <int MODE>
__global__ __launch_bounds__(256) void hgemm_kernel(const float* __restrict__ Af,
                                                    const float* __restrict__ Bf,
                                                    float* __restrict__ Cout) {
    extern __shared__ __half sm[];
    __half* As = sm;                 // [128][SPAD]
    __half* Bt = sm + 128 * SPAD;    // [128 n][SPAD k]
    int tid = threadIdx.x;
    long long rowBase = (long long)blockIdx.x * 128;

    // ---- stage A (convert to fp16 if MODE 0) ----
    if (MODE == 0) {
        for (int idx = tid; idx < 128 * 32; idx += 256) {     // float4 granules
            int row = idx >> 5, c4 = (idx & 31) * 4;
            long long gr = rowBase + row;
            float4 v = make_float4(0.f, 0.f, 0.f, 0.f);
            if (gr < NN) v = *(const float4*)(Af + (size_t)gr * 128 + c4);
            __half* p = As + row * SPAD + c4;
            p[0] = __float2half_rn(v.x); p[1] = __float2half_rn(v.y);
            p[2] = __float2half_rn(v.z); p[3] = __float2half_rn(v.w);
        }
    } else {
        for (int idx = tid; idx < 128 * 16; idx += 256) {     // uint4 = 8 halves
            int row = idx >> 4, c8 = (idx & 15) * 8;
            long long gr = rowBase + row;
            uint4 v = make_uint4(0u, 0u, 0u, 0u);
            if (gr < NN) v = *(const uint4*)(g_aggh + (size_t)gr * 128 + c8);
            *(uint4*)(As + row * SPAD + c8) = v;              // (row*SPAD+c8)*2 % 16 == 0
        }
    }
    // ---- stage B transposed: Bt[n][k] ----
    if (MODE == 0) {
        for (int idx = tid; idx < 128 * 32; idx += 256) {
            int k = idx >> 5, n4 = (idx & 31) * 4;
            float4 v = *(const float4*)(Bf + (size_t)k * 128 + n4);
            Bt[(n4 + 0) * SPAD + k] = __float2half_rn(v.x);
            Bt[(n4 + 1) * SPAD + k] = __float2half_rn(v.y);
            Bt[(n4 + 2) * SPAD + k] = __float2half_rn(v.z);
            Bt[(n4 + 3) * SPAD + k] = __float2half_rn(v.w);
        }
    } else {
        for (int idx = tid; idx < 128 * 16; idx += 256) {
            int k = idx >> 4, n8 = (idx & 15) * 8;
            uint4 v = *(const uint4*)(g_W2h + (size_t)k * 128 + n8);
            const __half* hv = reinterpret_cast<const __half*>(&v);
            #pragma unroll
            for (int j = 0; j < 8; j++) Bt[(n8 + j) * SPAD + k] = hv[j];
        }
    }
    __syncthreads();

    // ---- mma: warp w owns rows [w*16, w*16+16), all 128 cols ----
    int w = tid >> 5;
    int lane = tid & 31;
    int gid = lane >> 2;     // 0..7
    int tig = lane & 3;      // 0..3
    int wbase = w * 16;

    float c[16][4];
    #pragma unroll
    for (int n = 0; n < 16; n++)
        c[n][0] = c[n][1] = c[n][2] = c[n][3] = 0.f;

    #pragma unroll
    for (int k = 0; k < 8; k++) {
        int k16 = k * 16;
        unsigned a0 = *(const unsigned*)(As + (wbase + gid) * SPAD + k16 + tig * 2);
        unsigned a1 = *(const unsigned*)(As + (wbase + gid + 8) * SPAD + k16 + tig * 2);
        unsigned a2 = *(const unsigned*)(As + (wbase + gid) * SPAD + k16 + 8 + tig * 2);
        unsigned a3 = *(const unsigned*)(As + (wbase + gid + 8) * SPAD + k16 + 8 + tig * 2);
        #pragma unroll
        for (int n = 0; n < 16; n++) {
            unsigned b0 = *(const unsigned*)(Bt + (n * 8 + gid) * SPAD + k16 + tig * 2);
            unsigned b1 = *(const unsigned*)(Bt + (n * 8 + gid) * SPAD + k16 + 8 + tig * 2);
            asm volatile(
                "mma.sync.aligned.m16n8k16.row.col.f32.f16.f16.f32 "
                "{%0,%1,%2,%3}, {%4,%5,%6,%7}, {%8,%9}, {%0,%1,%2,%3};\n"
                : "+f"(c[n][0]), "+f"(c[n][1]), "+f"(c[n][2]), "+f"(c[n][3])
                : "r"(a0), "r"(a1), "r"(a2), "r"(a3), "r"(b0), "r"(b1));
        }
    }

    // ---- epilogue ----
    long long r0 = rowBase + wbase + gid;
    long long r1 = r0 + 8;
    #pragma unroll
    for (int n = 0; n < 16; n++) {
        int col = n * 8 + tig * 2;
        if (MODE == 0) {
            if (r0 < NN)
                *(__half2*)(g_h0h + (size_t)r0 * 128 + col) = __floats2half2_rn(c[n][0], c[n][1]);
            if (r1 < NN)
                *(__half2*)(g_h0h + (size_t)r1 * 128 + col) = __floats2half2_rn(c[n][2], c[n][3]);
        } else {
            float bb0 = g_b2[col], bb1 = g_b2[col + 1];
            float* base;
            int cc;
            if (col < OC) { base = Cout;            cc = col; }
            else          { base = Cout + HALF_OFF; cc = col - OC; }
            if (r0 < NN)
                *(float2*)(base + (size_t)r0 * OC + cc) = make_float2(c[n][0] + bb0, c[n][1] + bb1);
            if (r1 < NN)
                *(float2*)(base + (size_t)r1 * OC + cc) = make_float2(c[n][2] + bb0, c[n][3] + bb1);
        }
    }
}

// ---------------- launch ----------------
extern "C" void kernel_launch(void* const* d_in, const int* in_sizes, int n_in,
                              void* d_out, int out_size) {
    const float *x = 0, *W1 = 0, *b1 = 0, *Wmu = 0, *Wls = 0, *bmu = 0, *bls = 0;
    const void *ei = 0;
    for (int i = 0; i < n_in; i++) {
        long long s = in_sizes[i];
        if (s == 12800000LL)                        x  = (const float*)d_in[i];
        else if (s == 3200000LL || s == 6400000LL)  ei = d_in[i];
        else if (s == 16384LL)                      W1 = (const float*)d_in[i];
        else if (s == 128LL)                        b1 = (const float*)d_in[i];
        else if (s == 8192LL) { if (!Wmu) Wmu = (const float*)d_in[i]; else Wls = (const float*)d_in[i]; }
        else if (s == 64LL)   { if (!bmu) bmu = (const float*)d_in[i]; else bls = (const float*)d_in[i]; }
    }
    float* out = (float*)d_out;
    if (!x || !ei || !W1 || !b1 || !Wmu || !Wls || !bmu || !bls) return;  // Signal A
    if (!((long long)out_size == OUT_ELEMS || (long long)out_size == 4 * OUT_ELEMS)) {
        crash_kernel<<<1, 1>>>();  // Signal B
        return;
    }

    const int T = 256;
    int gemmBlocks = (NN + 127) / 128;       // 782
    int pullBlocks = (NN * 32 + T - 1) / T;  // 12500
    int smemBytes = 2 * 128 * SPAD * 2;      // 69632

    cudaFuncSetAttribute(hgemm_kernel<0>, cudaFuncAttributeMaxDynamicSharedMemorySize, smemBytes);
    cudaFuncSetAttribute(hgemm_kernel<1>, cudaFuncAttributeMaxDynamicSharedMemorySize, smemBytes);

    // edges + degrees + CSR
    init_kernel<<<400, T>>>();
    detect_kernel<<<256, T>>>((const unsigned int*)ei);
    convert_hist_kernel<<<4096, T>>>(ei);
    dinv_kernel<<<400, T>>>();
    scan1_kernel<<<SCAN_BLK, T>>>();
    scan2_kernel<<<1, 32>>>();
    scan3_kernel<<<SCAN_BLK, T>>>();
    fill_kernel<<<4096, T>>>();

    // layer 1: g_h0h = fp16(x @ W1) ; g_h1h = fp16(relu(pull(g_h0h) + b1))
    hgemm_kernel<0><<<gemmBlocks, T, smemBytes>>>(x, W1, nullptr);
    pull_kernel<1><<<pullBlocks, T>>>(b1);

    // layer 2: g_aggh = fp16(pull(g_h1h)) ; out = g_aggh @ g_W2h + g_b2 (split)
    pull_kernel<2><<<pullBlocks, T>>>(nullptr);
    pack_kernel<<<(CH * OC + T - 1) / T, T>>>(Wmu, Wls, bmu, bls);
    hgemm_kernel<1><<<gemmBlocks, T, smemBytes>>>(nullptr, nullptr, out);
}

// round 15
// speedup vs baseline: 1.5419x; 1.0316x over previous
#include <cuda_runtime.h>
#include <cuda_fp16.h>

#define NN 100000
#define CH 128
#define NE 1600000
#define OC 64
#define OUT_ELEMS (2LL * NN * OC)   // 12,800,000
#define HALF_OFF  (OUT_ELEMS / 2)   // 6,400,000
#define SCAN_BLK  391               // ceil(NN/256)
#define SPAD 136                    // padded K-stride in halves (conflict-free)

// Scratch (__device__ globals; NEVER passed as kernel args from host — GB300
// ATS makes the host-shadow silently valid-and-wrong).
__device__ __half g_h0h[(size_t)NN * CH]; // fp16(x@W1)
__device__ __half g_h1h[(size_t)NN * CH]; // fp16(relu(gcn1))
__device__ __half g_aggh[(size_t)NN * CH];// fp16(layer-2 aggregation)
__device__ float g_dinv[NN];
__device__ __half g_W2h[CH * CH];         // fp16 [W_mu | W_ls], row-major [k][n]
__device__ float g_b2[CH];                // [b_mu | b_ls]
__device__ int   g_count[NN];             // in-degree histogram
__device__ int   g_rowstart[NN + 1];      // CSR row offsets
__device__ int   g_cursor[NN];            // fill cursors
__device__ int   g_csr_src[NE];           // CSR: src per edge, grouped by dst
__device__ int   g_partial[SCAN_BLK];
__device__ unsigned int g_orflag;

__global__ void crash_kernel() { *((volatile int*)0) = 1; }  // out_size mismatch signal

// ---------------- init: zero counts + orflag ----------------
__global__ void init_kernel() {
    long long stride = (long long)gridDim.x * blockDim.x;
    long long i0 = (long long)blockIdx.x * blockDim.x + threadIdx.x;
    if (i0 == 0) g_orflag = 0u;
    for (long long i = i0; i < NN; i += stride) g_count[i] = 0;
}

// ---------------- edge dtype detect ----------------
// OR odd int32 words of first 2*NE words: int64 (vals < 2^31) -> all zero.
__global__ void detect_kernel(const unsigned int* __restrict__ ei32) {
    unsigned int acc = 0;
    long long stride = (long long)gridDim.x * blockDim.x;
    for (long long i = (long long)blockIdx.x * blockDim.x + threadIdx.x; i < NE; i += stride)
        acc |= ei32[2 * i + 1];
    #pragma unroll
    for (int o = 16; o > 0; o >>= 1) acc |= __shfl_down_sync(0xffffffffu, acc, o);
    if ((threadIdx.x & 31) == 0 && acc) atomicOr(&g_orflag, acc);
}

// ---------------- dst histogram (direct from raw edge buffer) ----------------
__global__ void hist_kernel(const void* __restrict__ ei) {
    long long stride = (long long)gridDim.x * blockDim.x;
    bool is64 = (g_orflag == 0u);
    for (long long e = (long long)blockIdx.x * blockDim.x + threadIdx.x; e < NE; e += stride) {
        int d = is64 ? (int)((const long long*)ei)[NE + e] : ((const int*)ei)[NE + e];
        if ((unsigned)d < (unsigned)NN) atomicAdd(&g_count[d], 1);
    }
}

// ---------------- CSR scan (3 stages); dinv fused into stage 1 ----------------
__global__ void scan1_kernel() {
    __shared__ int sh[256];
    int b = blockIdx.x, t = threadIdx.x;
    int i = b * 256 + t;
    int c = (i < NN) ? g_count[i] : 0;
    if (i < NN) g_dinv[i] = rsqrtf((float)c + 1.0f);   // fused dinv
    sh[t] = c;
    __syncthreads();
    #pragma unroll
    for (int o = 1; o < 256; o <<= 1) {
        int v = (t >= o) ? sh[t - o] : 0;
        __syncthreads();
        sh[t] += v;
        __syncthreads();
    }
    if (i < NN) g_rowstart[i] = sh[t] - c;
    if (t == 255) g_partial[b] = sh[t];
}

__global__ void scan2_kernel() {
    if (threadIdx.x == 0 && blockIdx.x == 0) {
        int run = 0;
        for (int b = 0; b < SCAN_BLK; b++) {
            int v = g_partial[b];
            g_partial[b] = run;
            run += v;
        }
        g_rowstart[NN] = run;
    }
}

__global__ void scan3_kernel() {
    int b = blockIdx.x, t = threadIdx.x;
    int i = b * 256 + t;
    if (i < NN) {
        int rs = g_rowstart[i] + g_partial[b];
        g_rowstart[i] = rs;
        g_cursor[i] = rs;
    }
}

// ---------------- CSR fill (direct from raw edge buffer) ----------------
__global__ void fill_kernel(const void* __restrict__ ei) {
    long long stride = (long long)gridDim.x * blockDim.x;
    bool is64 = (g_orflag == 0u);
    for (long long e = (long long)blockIdx.x * blockDim.x + threadIdx.x; e < NE; e += stride) {
        int s, d;
        if (is64) {
            s = (int)((const long long*)ei)[e];
            d = (int)((const long long*)ei)[NE + e];
        } else {
            s = ((const int*)ei)[e];
            d = ((const int*)ei)[NE + e];
        }
        if ((unsigned)s >= (unsigned)NN || (unsigned)d >= (unsigned)NN) continue;
        int pos = atomicAdd(&g_cursor[d], 1);
        g_csr_src[pos] = s;
    }
}

// ---------------- pull aggregation: warp per node, fp16 gather ----------------
// LAYER==1: reads g_h0h, writes g_h1h = fp16(relu(... + b1)).
// LAYER==2: reads g_h1h, writes g_aggh = fp16(...).
template <int LAYER>
__global__ void pull_kernel(const float* __restrict__ b1) {
    long long gt = (long long)blockIdx.x * blockDim.x + threadIdx.x;
    int n = (int)(gt >> 5);
    int lane = (int)(gt & 31);
    if (n >= NN) return;
    const __half* H = (LAYER == 1) ? g_h0h : g_h1h;
    int row = g_rowstart[n];
    int end = g_rowstart[n + 1];
    float4 acc = make_float4(0.f, 0.f, 0.f, 0.f);
    #pragma unroll 2
    for (int e = row; e < end; e++) {
        int s = g_csr_src[e];
        float ws = g_dinv[s];
        uint2 raw = *(const uint2*)(H + (size_t)s * CH + lane * 4);
        float2 f0 = __half22float2(*reinterpret_cast<__half2*>(&raw.x));
        float2 f1 = __half22float2(*reinterpret_cast<__half2*>(&raw.y));
        acc.x = fmaf(ws, f0.x, acc.x);
        acc.y = fmaf(ws, f0.y, acc.y);
        acc.z = fmaf(ws, f1.x, acc.z);
        acc.w = fmaf(ws, f1.y, acc.w);
    }
    float dd = g_dinv[n];
    uint2 rawd = *(const uint2*)(H + (size_t)n * CH + lane * 4);
    float2 h0 = __half22float2(*reinterpret_cast<__half2*>(&rawd.x));
    float2 h1 = __half22float2(*reinterpret_cast<__half2*>(&rawd.y));
    float4 r;
    r.x = dd * acc.x + dd * dd * h0.x;
    r.y = dd * acc.y + dd * dd * h0.y;
    r.z = dd * acc.z + dd * dd * h1.x;
    r.w = dd * acc.w + dd * dd * h1.y;
    uint2 outp;
    if (LAYER == 1) {
        float4 b = ((const float4*)b1)[lane];
        r.x = fmaxf(r.x + b.x, 0.f);
        r.y = fmaxf(r.y + b.y, 0.f);
        r.z = fmaxf(r.z + b.z, 0.f);
        r.w = fmaxf(r.w + b.w, 0.f);
        *reinterpret_cast<__half2*>(&outp.x) = __floats2half2_rn(r.x, r.y);
        *reinterpret_cast<__half2*>(&outp.y) = __floats2half2_rn(r.z, r.w);
        *(uint2*)(g_h1h + (size_t)n * CH + lane * 4) = outp;
    } else {
        *reinterpret_cast<__half2*>(&outp.x) = __floats2half2_rn(r.x, r.y);
        *reinterpret_cast<__half2*>(&outp.y) = __floats2half2_rn(r.z, r.w);
        *(uint2*)(g_aggh + (size_t)n * CH + lane * 4) = outp;
    }
}

// ---------------- pack [W_mu|W_ls] -> fp16 g_W2h, [b_mu|b_ls] -> g_b2 ----------------
__global__ void pack_kernel(const float* __restrict__ Wmu, const float* __restrict__ Wls,
                            const float* __restrict__ bmu, const float* __restrict__ bls) {
    int i = blockIdx.x * blockDim.x + threadIdx.x;
    if (i < CH * OC) {
        int r = i / OC, c = i % OC;
        g_W2h[r * CH + c]      = __float2half_rn(Wmu[i]);
        g_W2h[r * CH + OC + c] = __float2half_rn(Wls[i]);
    }
    if (i < OC) {
        g_b2[i]      = bmu[i];
        g_b2[OC + i] = bls[i];
    }
}

// ---------------- HMMA GEMM: C[M x 128] = A[M x 128] @ B[128 x 128] ----------------
// mma.sync.m16n8k16 f16*f16->f32. Block 256 thr (8 warps), tile 128 rows.
// MODE 0: A = x (fp32 arg), B = W1 (fp32 arg), out -> g_h0h fp16.
// MODE 1: A = g_aggh (fp16 symbol), B = g_W2h (fp16 symbol), out -> bias+split fp32.
template <int MODE>
__global__ __launch_bounds__(256) void hgemm_kernel(const float* __restrict__ Af,
                                                    const float* __restrict__ Bf,
                                                    float* __restrict__ Cout) {
    extern __shared__ __half sm[];
    __half* As = sm;                 // [128][SPAD]
    __half* Bt = sm + 128 * SPAD;    // [128 n][SPAD k]
    int tid = threadIdx.x;
    long long rowBase = (long long)blockIdx.x * 128;

    if (MODE == 0) {
        for (int idx = tid; idx < 128 * 32; idx += 256) {
            int row = idx >> 5, c4 = (idx & 31) * 4;
            long long gr = rowBase + row;
            float4 v = make_float4(0.f, 0.f, 0.f, 0.f);
            if (gr < NN) v = *(const float4*)(Af + (size_t)gr * 128 + c4);
            __half* p = As + row * SPAD + c4;
            p[0] = __float2half_rn(v.x); p[1] = __float2half_rn(v.y);
            p[2] = __float2half_rn(v.z); p[3] = __float2half_rn(v.w);
        }
        for (int idx = tid; idx < 128 * 32; idx += 256) {
            int k = idx >> 5, n4 = (idx & 31) * 4;
            float4 v = *(const float4*)(Bf + (size_t)k * 128 + n4);
            Bt[(n4 + 0) * SPAD + k] = __float2half_rn(v.x);
            Bt[(n4 + 1) * SPAD + k] = __float2half_rn(v.y);
            Bt[(n4 + 2) * SPAD + k] = __float2half_rn(v.z);
            Bt[(n4 + 3) * SPAD + k] = __float2half_rn(v.w);
        }
    } else {
        for (int idx = tid; idx < 128 * 16; idx += 256) {
            int row = idx >> 4, c8 = (idx & 15) * 8;
            long long gr = rowBase + row;
            uint4 v = make_uint4(0u, 0u, 0u, 0u);
            if (gr < NN) v = *(const uint4*)(g_aggh + (size_t)gr * 128 + c8);
            *(uint4*)(As + row * SPAD + c8) = v;
        }
        for (int idx = tid; idx < 128 * 16; idx += 256) {
            int k = idx >> 4, n8 = (idx & 15) * 8;
            uint4 v = *(const uint4*)(g_W2h + (size_t)k * 128 + n8);
            const __half* hv = reinterpret_cast<const __half*>(&v);
            #pragma unroll
            for (int j = 0; j < 8; j++) Bt[(n8 + j) * SPAD + k] = hv[j];
        }
    }
    __syncthreads();

    int w = tid >> 5;
    int lane = tid & 31;
    int gid = lane >> 2;
    int tig = lane & 3;
    int wbase = w * 16;

    float c[16][4];
    #pragma unroll
    for (int n = 0; n < 16; n++)
        c[n][0] = c[n][1] = c[n][2] = c[n][3] = 0.f;

    #pragma unroll
    for (int k = 0; k < 8; k++) {
        int k16 = k * 16;
        unsigned a0 = *(const unsigned*)(As + (wbase + gid) * SPAD + k16 + tig * 2);
        unsigned a1 = *(const unsigned*)(As + (wbase + gid + 8) * SPAD + k16 + tig * 2);
        unsigned a2 = *(const unsigned*)(As + (wbase + gid) * SPAD + k16 + 8 + tig * 2);
        unsigned a3 = *(const unsigned*)(As + (wbase + gid + 8) * SPAD + k16 + 8 + tig * 2);
        #pragma unroll
        for (int n = 0; n < 16; n++) {
            unsigned b0 = *(const unsigned*)(Bt + (n * 8 + gid) * SPAD + k16 + tig * 2);
            unsigned b1 = *(const unsigned*)(Bt + (n * 8 + gid) * SPAD + k16 + 8 + tig * 2);
            asm volatile(
                "mma.sync.aligned.m16n8k16.row.col.f32.f16.f16.f32 "
                "{%0,%1,%2,%3}, {%4,%5,%6,%7}, {%8,%9}, {%0,%1,%2,%3};\n"
                : "+f"(c[n][0]), "+f"(c[n][1]), "+f"(c[n][2]), "+f"(c[n][3])
                : "r"(a0), "r"(a1), "r"(a2), "r"(a3), "r"(b0), "r"(b1));
        }
    }

    long long r0 = rowBase + wbase + gid;
    long long r1 = r0 + 8;
    #pragma unroll
    for (int n = 0; n < 16; n++) {
        int col = n * 8 + tig * 2;
        if (MODE == 0) {
            if (r0 < NN)
                *(__half2*)(g_h0h + (size_t)r0 * 128 + col) = __floats2half2_rn(c[n][0], c[n][1]);
            if (r1 < NN)
                *(__half2*)(g_h0h + (size_t)r1 * 128 + col) = __floats2half2_rn(c[n][2], c[n][3]);
        } else {
            float bb0 = g_b2[col], bb1 = g_b2[col + 1];
            float* base;
            int cc;
            if (col < OC) { base = Cout;            cc = col; }
            else          { base = Cout + HALF_OFF; cc = col - OC; }
            if (r0 < NN)
                *(float2*)(base + (size_t)r0 * OC + cc) = make_float2(c[n][0] + bb0, c[n][1] + bb1);
            if (r1 < NN)
                *(float2*)(base + (size_t)r1 * OC + cc) = make_float2(c[n][2] + bb0, c[n][3] + bb1);
        }
    }
}

// ---------------- launch ----------------
extern "C" void kernel_launch(void* const* d_in, const int* in_sizes, int n_in,
                              void* d_out, int out_size) {
    const float *x = 0, *W1 = 0, *b1 = 0, *Wmu = 0, *Wls = 0, *bmu = 0, *bls = 0;
    const void *ei = 0;
    for (int i = 0; i < n_in; i++) {
        long long s = in_sizes[i];
        if (s == 12800000LL)                        x  = (const float*)d_in[i];
        else if (s == 3200000LL || s == 6400000LL)  ei = d_in[i];
        else if (s == 16384LL)                      W1 = (const float*)d_in[i];
        else if (s == 128LL)                        b1 = (const float*)d_in[i];
        else if (s == 8192LL) { if (!Wmu) Wmu = (const float*)d_in[i]; else Wls = (const float*)d_in[i]; }
        else if (s == 64LL)   { if (!bmu) bmu = (const float*)d_in[i]; else bls = (const float*)d_in[i]; }
    }
    float* out = (float*)d_out;
    if (!x || !ei || !W1 || !b1 || !Wmu || !Wls || !bmu || !bls) return;  // Signal A
    if (!((long long)out_size == OUT_ELEMS || (long long)out_size == 4 * OUT_ELEMS)) {
        crash_kernel<<<1, 1>>>();  // Signal B
        return;
    }

    const int T = 256;
    int gemmBlocks = (NN + 127) / 128;       // 782
    int pullBlocks = (NN * 32 + T - 1) / T;  // 12500
    int smemBytes = 2 * 128 * SPAD * 2;      // 69632

    cudaFuncSetAttribute(hgemm_kernel<0>, cudaFuncAttributeMaxDynamicSharedMemorySize, smemBytes);
    cudaFuncSetAttribute(hgemm_kernel<1>, cudaFuncAttributeMaxDynamicSharedMemorySize, smemBytes);

    // edges + degrees + CSR (no intermediate g_eidx copy)
    init_kernel<<<400, T>>>();
    detect_kernel<<<256, T>>>((const unsigned int*)ei);
    hist_kernel<<<4096, T>>>(ei);
    scan1_kernel<<<SCAN_BLK, T>>>();        // also computes dinv
    scan2_kernel<<<1, 32>>>();
    scan3_kernel<<<SCAN_BLK, T>>>();
    fill_kernel<<<4096, T>>>(ei);

    // layer 1: g_h0h = fp16(x @ W1) ; g_h1h = fp16(relu(pull(g_h0h) + b1))
    hgemm_kernel<0><<<gemmBlocks, T, smemBytes>>>(x, W1, nullptr);
    pull_kernel<1><<<pullBlocks, T>>>(b1);

    // layer 2: g_aggh = fp16(pull(g_h1h)) ; out = g_aggh @ g_W2h + g_b2 (split)
    pull_kernel<2><<<pullBlocks, T>>>(nullptr);
    pack_kernel<<<(CH * OC + T - 1) / T, T>>>(Wmu, Wls, bmu, bls);
    hgemm_kernel<1><<<gemmBlocks, T, smemBytes>>>(nullptr, nullptr, out);
}

// round 16
// speedup vs baseline: 1.5975x; 1.0361x over previous
#include <cuda_runtime.h>
#include <cuda_fp16.h>

#define NN 100000
#define CH 128
#define NE 1600000
#define OC 64
#define OUT_ELEMS (2LL * NN * OC)   // 12,800,000
#define HALF_OFF  (OUT_ELEMS / 2)   // 6,400,000
#define SCAN_BLK  391               // ceil(NN/256)
#define SPAD 136                    // padded K-stride in halves (conflict-free)

// Scratch (__device__ globals; NEVER passed as kernel args from host — GB300
// ATS makes the host-shadow silently valid-and-wrong).
// P-representation: stored features are pre-scaled by dinv[n].
__device__ __half g_P0[(size_t)NN * CH];  // dinv[n] * (x@W1)[n]
__device__ __half g_P1[(size_t)NN * CH];  // dinv[n] * relu(gcn1)[n]
__device__ __half g_aggh[(size_t)NN * CH];// fp16(layer-2 aggregation), plain
__device__ float g_dinv[NN];
__device__ __half g_W2h[CH * CH];         // fp16 [W_mu | W_ls], row-major [k][n]
__device__ float g_b2[CH];                // [b_mu | b_ls]
__device__ int   g_count[NN];             // in-degree histogram
__device__ int   g_rowstart[NN + 1];      // CSR row offsets
__device__ int   g_cursor[NN];            // fill cursors
__device__ int   g_csr_src[NE];           // CSR: src per edge, grouped by dst
__device__ int   g_partial[SCAN_BLK];
__device__ unsigned int g_orflag;

__global__ void crash_kernel() { *((volatile int*)0) = 1; }  // out_size mismatch signal

// ---------------- init: zero counts + orflag ----------------
__global__ void init_kernel() {
    long long stride = (long long)gridDim.x * blockDim.x;
    long long i0 = (long long)blockIdx.x * blockDim.x + threadIdx.x;
    if (i0 == 0) g_orflag = 0u;
    for (long long i = i0; i < NN; i += stride) g_count[i] = 0;
}

// ---------------- edge dtype detect ----------------
// OR odd int32 words of first 2*NE words: int64 (vals < 2^31) -> all zero.
__global__ void detect_kernel(const unsigned int* __restrict__ ei32) {
    unsigned int acc = 0;
    long long stride = (long long)gridDim.x * blockDim.x;
    for (long long i = (long long)blockIdx.x * blockDim.x + threadIdx.x; i < NE; i += stride)
        acc |= ei32[2 * i + 1];
    #pragma unroll
    for (int o = 16; o > 0; o >>= 1) acc |= __shfl_down_sync(0xffffffffu, acc, o);
    if ((threadIdx.x & 31) == 0 && acc) atomicOr(&g_orflag, acc);
}

// ---------------- dst histogram (direct from raw edge buffer) ----------------
__global__ void hist_kernel(const void* __restrict__ ei) {
    long long stride = (long long)gridDim.x * blockDim.x;
    bool is64 = (g_orflag == 0u);
    for (long long e = (long long)blockIdx.x * blockDim.x + threadIdx.x; e < NE; e += stride) {
        int d = is64 ? (int)((const long long*)ei)[NE + e] : ((const int*)ei)[NE + e];
        if ((unsigned)d < (unsigned)NN) atomicAdd(&g_count[d], 1);
    }
}

// ---------------- CSR scan (3 stages); dinv fused into stage 1 ----------------
__global__ void scan1_kernel() {
    __shared__ int sh[256];
    int b = blockIdx.x, t = threadIdx.x;
    int i = b * 256 + t;
    int c = (i < NN) ? g_count[i] : 0;
    if (i < NN) g_dinv[i] = rsqrtf((float)c + 1.0f);   // fused dinv
    sh[t] = c;
    __syncthreads();
    #pragma unroll
    for (int o = 1; o < 256; o <<= 1) {
        int v = (t >= o) ? sh[t - o] : 0;
        __syncthreads();
        sh[t] += v;
        __syncthreads();
    }
    if (i < NN) g_rowstart[i] = sh[t] - c;
    if (t == 255) g_partial[b] = sh[t];
}

__global__ void scan2_kernel() {
    if (threadIdx.x == 0 && blockIdx.x == 0) {
        int run = 0;
        for (int b = 0; b < SCAN_BLK; b++) {
            int v = g_partial[b];
            g_partial[b] = run;
            run += v;
        }
        g_rowstart[NN] = run;
    }
}

__global__ void scan3_kernel() {
    int b = blockIdx.x, t = threadIdx.x;
    int i = b * 256 + t;
    if (i < NN) {
        int rs = g_rowstart[i] + g_partial[b];
        g_rowstart[i] = rs;
        g_cursor[i] = rs;
    }
}

// ---------------- CSR fill (direct from raw edge buffer) ----------------
__global__ void fill_kernel(const void* __restrict__ ei) {
    long long stride = (long long)gridDim.x * blockDim.x;
    bool is64 = (g_orflag == 0u);
    for (long long e = (long long)blockIdx.x * blockDim.x + threadIdx.x; e < NE; e += stride) {
        int s, d;
        if (is64) {
            s = (int)((const long long*)ei)[e];
            d = (int)((const long long*)ei)[NE + e];
        } else {
            s = ((const int*)ei)[e];
            d = ((const int*)ei)[NE + e];
        }
        if ((unsigned)s >= (unsigned)NN || (unsigned)d >= (unsigned)NN) continue;
        int pos = atomicAdd(&g_cursor[d], 1);
        g_csr_src[pos] = s;
    }
}

// ---------------- pull aggregation: warp per node, fp16 gather, pre-scaled P ----
// acc = Sum_{s in in(d)} P[s] + P[d];  r = dinv[d] * acc
// LAYER==1: reads g_P0, writes g_P1 = fp16(dinv * relu(r + b1)).
// LAYER==2: reads g_P1, writes g_aggh = fp16(r).
template <int LAYER>
__global__ void pull_kernel(const float* __restrict__ b1) {
    long long gt = (long long)blockIdx.x * blockDim.x + threadIdx.x;
    int n = (int)(gt >> 5);
    int lane = (int)(gt & 31);
    if (n >= NN) return;
    const __half* H = (LAYER == 1) ? g_P0 : g_P1;
    int row = g_rowstart[n];
    int end = g_rowstart[n + 1];
    float4 acc = make_float4(0.f, 0.f, 0.f, 0.f);
    #pragma unroll 2
    for (int e = row; e < end; e++) {
        int s = g_csr_src[e];
        uint2 raw = *(const uint2*)(H + (size_t)s * CH + lane * 4);
        float2 f0 = __half22float2(*reinterpret_cast<__half2*>(&raw.x));
        float2 f1 = __half22float2(*reinterpret_cast<__half2*>(&raw.y));
        acc.x += f0.x;
        acc.y += f0.y;
        acc.z += f1.x;
        acc.w += f1.y;
    }
    // self-loop: + P[d]
    uint2 rawd = *(const uint2*)(H + (size_t)n * CH + lane * 4);
    float2 h0 = __half22float2(*reinterpret_cast<__half2*>(&rawd.x));
    float2 h1 = __half22float2(*reinterpret_cast<__half2*>(&rawd.y));
    acc.x += h0.x; acc.y += h0.y; acc.z += h1.x; acc.w += h1.y;
    float dd = g_dinv[n];
    float4 r = make_float4(dd * acc.x, dd * acc.y, dd * acc.z, dd * acc.w);
    uint2 outp;
    if (LAYER == 1) {
        float4 b = ((const float4*)b1)[lane];
        r.x = dd * fmaxf(r.x + b.x, 0.f);   // store P1 = dinv * relu(...)
        r.y = dd * fmaxf(r.y + b.y, 0.f);
        r.z = dd * fmaxf(r.z + b.z, 0.f);
        r.w = dd * fmaxf(r.w + b.w, 0.f);
        *reinterpret_cast<__half2*>(&outp.x) = __floats2half2_rn(r.x, r.y);
        *reinterpret_cast<__half2*>(&outp.y) = __floats2half2_rn(r.z, r.w);
        *(uint2*)(g_P1 + (size_t)n * CH + lane * 4) = outp;
    } else {
        *reinterpret_cast<__half2*>(&outp.x) = __floats2half2_rn(r.x, r.y);
        *reinterpret_cast<__half2*>(&outp.y) = __floats2half2_rn(r.z, r.w);
        *(uint2*)(g_aggh + (size_t)n * CH + lane * 4) = outp;
    }
}

// ---------------- pack [W_mu|W_ls] -> fp16 g_W2h, [b_mu|b_ls] -> g_b2 ----------------
__global__ void pack_kernel(const float* __restrict__ Wmu, const float* __restrict__ Wls,
                            const float* __restrict__ bmu, const float* __restrict__ bls) {
    int i = blockIdx.x * blockDim.x + threadIdx.x;
    if (i < CH * OC) {
        int r = i / OC, c = i % OC;
        g_W2h[r * CH + c]      = __float2half_rn(Wmu[i]);
        g_W2h[r * CH + OC + c] = __float2half_rn(Wls[i]);
    }
    if (i < OC) {
        g_b2[i]      = bmu[i];
        g_b2[OC + i] = bls[i];
    }
}

// ---------------- HMMA GEMM: C[M x 128] = A[M x 128] @ B[128 x 128] ----------------
// mma.sync.m16n8k16 f16*f16->f32. Block 256 thr (8 warps), tile 128 rows.
// MODE 0: A = x (fp32 arg), B = W1 (fp32 arg), out -> g_P0 = dinv*(x@W1) fp16.
// MODE 1: A = g_aggh (fp16 symbol), B = g_W2h (fp16 symbol), out -> bias+split fp32.
template <int MODE>
__global__ __launch_bounds__(256) void hgemm_kernel(const float* __restrict__ Af,
                                                    const float* __restrict__ Bf,
                                                    float* __restrict__ Cout) {
    extern __shared__ __half sm[];
    __half* As = sm;                 // [128][SPAD]
    __half* Bt = sm + 128 * SPAD;    // [128 n][SPAD k]
    int tid = threadIdx.x;
    long long rowBase = (long long)blockIdx.x * 128;

    if (MODE == 0) {
        for (int idx = tid; idx < 128 * 32; idx += 256) {
            int row = idx >> 5, c4 = (idx & 31) * 4;
            long long gr = rowBase + row;
            float4 v = make_float4(0.f, 0.f, 0.f, 0.f);
            if (gr < NN) v = *(const float4*)(Af + (size_t)gr * 128 + c4);
            __half* p = As + row * SPAD + c4;
            p[0] = __float2half_rn(v.x); p[1] = __float2half_rn(v.y);
            p[2] = __float2half_rn(v.z); p[3] = __float2half_rn(v.w);
        }
        for (int idx = tid; idx < 128 * 32; idx += 256) {
            int k = idx >> 5, n4 = (idx & 31) * 4;
            float4 v = *(const float4*)(Bf + (size_t)k * 128 + n4);
            Bt[(n4 + 0) * SPAD + k] = __float2half_rn(v.x);
            Bt[(n4 + 1) * SPAD + k] = __float2half_rn(v.y);
            Bt[(n4 + 2) * SPAD + k] = __float2half_rn(v.z);
            Bt[(n4 + 3) * SPAD + k] = __float2half_rn(v.w);
        }
    } else {
        for (int idx = tid; idx < 128 * 16; idx += 256) {
            int row = idx >> 4, c8 = (idx & 15) * 8;
            long long gr = rowBase + row;
            uint4 v = make_uint4(0u, 0u, 0u, 0u);
            if (gr < NN) v = *(const uint4*)(g_aggh + (size_t)gr * 128 + c8);
            *(uint4*)(As + row * SPAD + c8) = v;
        }
        for (int idx = tid; idx < 128 * 16; idx += 256) {
            int k = idx >> 4, n8 = (idx & 15) * 8;
            uint4 v = *(const uint4*)(g_W2h + (size_t)k * 128 + n8);
            const __half* hv = reinterpret_cast<const __half*>(&v);
            #pragma unroll
            for (int j = 0; j < 8; j++) Bt[(n8 + j) * SPAD + k] = hv[j];
        }
    }
    __syncthreads();

    int w = tid >> 5;
    int lane = tid & 31;
    int gid = lane >> 2;
    int tig = lane & 3;
    int wbase = w * 16;

    float c[16][4];
    #pragma unroll
    for (int n = 0; n < 16; n++)
        c[n][0] = c[n][1] = c[n][2] = c[n][3] = 0.f;

    #pragma unroll
    for (int k = 0; k < 8; k++) {
        int k16 = k * 16;
        unsigned a0 = *(const unsigned*)(As + (wbase + gid) * SPAD + k16 + tig * 2);
        unsigned a1 = *(const unsigned*)(As + (wbase + gid + 8) * SPAD + k16 + tig * 2);
        unsigned a2 = *(const unsigned*)(As + (wbase + gid) * SPAD + k16 + 8 + tig * 2);
        unsigned a3 = *(const unsigned*)(As + (wbase + gid + 8) * SPAD + k16 + 8 + tig * 2);
        #pragma unroll
        for (int n = 0; n < 16; n++) {
            unsigned b0 = *(const unsigned*)(Bt + (n * 8 + gid) * SPAD + k16 + tig * 2);
            unsigned b1 = *(const unsigned*)(Bt + (n * 8 + gid) * SPAD + k16 + 8 + tig * 2);
            asm volatile(
                "mma.sync.aligned.m16n8k16.row.col.f32.f16.f16.f32 "
                "{%0,%1,%2,%3}, {%4,%5,%6,%7}, {%8,%9}, {%0,%1,%2,%3};\n"
                : "+f"(c[n][0]), "+f"(c[n][1]), "+f"(c[n][2]), "+f"(c[n][3])
                : "r"(a0), "r"(a1), "r"(a2), "r"(a3), "r"(b0), "r"(b1));
        }
    }

    long long r0 = rowBase + wbase + gid;
    long long r1 = r0 + 8;
    float d0 = (MODE == 0 && r0 < NN) ? g_dinv[r0] : 0.f;
    float d1 = (MODE == 0 && r1 < NN) ? g_dinv[r1] : 0.f;
    #pragma unroll
    for (int n = 0; n < 16; n++) {
        int col = n * 8 + tig * 2;
        if (MODE == 0) {
            if (r0 < NN)
                *(__half2*)(g_P0 + (size_t)r0 * 128 + col) =
                    __floats2half2_rn(d0 * c[n][0], d0 * c[n][1]);
            if (r1 < NN)
                *(__half2*)(g_P0 + (size_t)r1 * 128 + col) =
                    __floats2half2_rn(d1 * c[n][2], d1 * c[n][3]);
        } else {
            float bb0 = g_b2[col], bb1 = g_b2[col + 1];
            float* base;
            int cc;
            if (col < OC) { base = Cout;            cc = col; }
            else          { base = Cout + HALF_OFF; cc = col - OC; }
            if (r0 < NN)
                *(float2*)(base + (size_t)r0 * OC + cc) = make_float2(c[n][0] + bb0, c[n][1] + bb1);
            if (r1 < NN)
                *(float2*)(base + (size_t)r1 * OC + cc) = make_float2(c[n][2] + bb0, c[n][3] + bb1);
        }
    }
}

// ---------------- launch ----------------
extern "C" void kernel_launch(void* const* d_in, const int* in_sizes, int n_in,
                              void* d_out, int out_size) {
    const float *x = 0, *W1 = 0, *b1 = 0, *Wmu = 0, *Wls = 0, *bmu = 0, *bls = 0;
    const void *ei = 0;
    for (int i = 0; i < n_in; i++) {
        long long s = in_sizes[i];
        if (s == 12800000LL)                        x  = (const float*)d_in[i];
        else if (s == 3200000LL || s == 6400000LL)  ei = d_in[i];
        else if (s == 16384LL)                      W1 = (const float*)d_in[i];
        else if (s == 128LL)                        b1 = (const float*)d_in[i];
        else if (s == 8192LL) { if (!Wmu) Wmu = (const float*)d_in[i]; else Wls = (const float*)d_in[i]; }
        else if (s == 64LL)   { if (!bmu) bmu = (const float*)d_in[i]; else bls = (const float*)d_in[i]; }
    }
    float* out = (float*)d_out;
    if (!x || !ei || !W1 || !b1 || !Wmu || !Wls || !bmu || !bls) return;  // Signal A
    if (!((long long)out_size == OUT_ELEMS || (long long)out_size == 4 * OUT_ELEMS)) {
        crash_kernel<<<1, 1>>>();  // Signal B
        return;
    }

    const int T = 256;
    int gemmBlocks = (NN + 127) / 128;       // 782
    int pullBlocks = (NN * 32 + T - 1) / T;  // 12500
    int smemBytes = 2 * 128 * SPAD * 2;      // 69632

    cudaFuncSetAttribute(hgemm_kernel<0>, cudaFuncAttributeMaxDynamicSharedMemorySize, smemBytes);
    cudaFuncSetAttribute(hgemm_kernel<1>, cudaFuncAttributeMaxDynamicSharedMemorySize, smemBytes);

    // edges + degrees + CSR (dinv computed in scan1, BEFORE gemm1 needs it)
    init_kernel<<<400, T>>>();
    detect_kernel<<<256, T>>>((const unsigned int*)ei);
    hist_kernel<<<4096, T>>>(ei);
    scan1_kernel<<<SCAN_BLK, T>>>();        // also computes dinv
    scan2_kernel<<<1, 32>>>();
    scan3_kernel<<<SCAN_BLK, T>>>();
    fill_kernel<<<4096, T>>>(ei);

    // layer 1: g_P0 = fp16(dinv * (x @ W1)) ; g_P1 = fp16(dinv * relu(pull + b1))
    hgemm_kernel<0><<<gemmBlocks, T, smemBytes>>>(x, W1, nullptr);
    pull_kernel<1><<<pullBlocks, T>>>(b1);

    // layer 2: g_aggh = fp16(pull(g_P1)) ; out = g_aggh @ g_W2h + g_b2 (split)
    pull_kernel<2><<<pullBlocks, T>>>(nullptr);
    pack_kernel<<<(CH * OC + T - 1) / T, T>>>(Wmu, Wls, bmu, bls);
    hgemm_kernel<1><<<gemmBlocks, T, smemBytes>>>(nullptr, nullptr, out);
}

// round 17
// speedup vs baseline: 1.6516x; 1.0338x over previous
#include <cuda_runtime.h>
#include <cuda_fp16.h>

#define NN 100000
#define CH 128
#define NE 1600000
#define OC 64
#define OUT_ELEMS (2LL * NN * OC)   // 12,800,000
#define HALF_OFF  (OUT_ELEMS / 2)   // 6,400,000
#define SCAN_BLK  391               // ceil(NN/256)
#define SPAD 136                    // padded K-stride in halves (conflict-free)

// Scratch (__device__ globals; NEVER passed as kernel args from host — GB300
// ATS makes the host-shadow silently valid-and-wrong).
// P-representation: stored features are pre-scaled by dinv[n].
__device__ __half g_P0[(size_t)NN * CH];  // dinv[n] * (x@W1)[n]
__device__ __half g_P1[(size_t)NN * CH];  // dinv[n] * relu(gcn1)[n]
__device__ __half g_aggh[(size_t)NN * CH];// fp16(layer-2 aggregation), plain
__device__ float g_dinv[NN];
__device__ int   g_count[NN];             // in-degree histogram
__device__ int   g_rowstart[NN + 1];      // CSR row offsets
__device__ int   g_cursor[NN];            // fill cursors
__device__ int   g_csr_src[NE];           // CSR: src per edge, grouped by dst
__device__ int   g_partial[SCAN_BLK];
__device__ unsigned int g_orflag;

__global__ void crash_kernel() { *((volatile int*)0) = 1; }  // out_size mismatch signal

// ---------------- init counts + sampled dtype detect (single kernel) ----------------
// Block 0 additionally samples 4096 odd int32 words of the src half:
// int64 data (vals < 2^31) -> all high-halves zero; int32 -> nonzero w.p. 1.
__global__ void initdetect_kernel(const unsigned int* __restrict__ ei32) {
    if (blockIdx.x == 0) {
        __shared__ unsigned int sacc[256];
        unsigned int acc = 0;
        for (int i = threadIdx.x; i < 4096; i += 256) acc |= ei32[2 * i + 1];
        sacc[threadIdx.x] = acc;
        __syncthreads();
        #pragma unroll
        for (int o = 128; o > 0; o >>= 1) {
            if (threadIdx.x < o) sacc[threadIdx.x] |= sacc[threadIdx.x + o];
            __syncthreads();
        }
        if (threadIdx.x == 0) g_orflag = sacc[0];
    }
    long long stride = (long long)gridDim.x * blockDim.x;
    for (long long i = (long long)blockIdx.x * blockDim.x + threadIdx.x; i < NN; i += stride)
        g_count[i] = 0;
}

// ---------------- dst histogram (direct from raw edge buffer) ----------------
__global__ void hist_kernel(const void* __restrict__ ei) {
    long long stride = (long long)gridDim.x * blockDim.x;
    bool is64 = (g_orflag == 0u);
    for (long long e = (long long)blockIdx.x * blockDim.x + threadIdx.x; e < NE; e += stride) {
        int d = is64 ? (int)((const long long*)ei)[NE + e] : ((const int*)ei)[NE + e];
        if ((unsigned)d < (unsigned)NN) atomicAdd(&g_count[d], 1);
    }
}

// ---------------- CSR scan stage 1 (per-block scan + dinv) ----------------
__global__ void scan1_kernel() {
    __shared__ int sh[256];
    int b = blockIdx.x, t = threadIdx.x;
    int i = b * 256 + t;
    int c = (i < NN) ? g_count[i] : 0;
    if (i < NN) g_dinv[i] = rsqrtf((float)c + 1.0f);   // fused dinv
    sh[t] = c;
    __syncthreads();
    #pragma unroll
    for (int o = 1; o < 256; o <<= 1) {
        int v = (t >= o) ? sh[t - o] : 0;
        __syncthreads();
        sh[t] += v;
        __syncthreads();
    }
    if (i < NN) g_rowstart[i] = sh[t] - c;
    if (t == 255) g_partial[b] = sh[t];
}

// ---------------- CSR scan stages 2+3 fused: decoupled base per block ----------------
__global__ void scan23_kernel() {
    __shared__ int sh[256];
    int b = blockIdx.x, t = threadIdx.x;
    int s = 0;
    for (int j = t; j < b; j += 256) s += g_partial[j];   // L2-hit loads, <=391
    sh[t] = s;
    __syncthreads();
    #pragma unroll
    for (int o = 128; o > 0; o >>= 1) {
        if (t < o) sh[t] += sh[t + o];
        __syncthreads();
    }
    int base = sh[0];
    int i = b * 256 + t;
    if (i < NN) {
        int rs = g_rowstart[i] + base;
        g_rowstart[i] = rs;
        g_cursor[i] = rs;
    }
    if (b == SCAN_BLK - 1 && t == 0)
        g_rowstart[NN] = base + g_partial[b];
}

// ---------------- CSR fill (direct from raw edge buffer) ----------------
__global__ void fill_kernel(const void* __restrict__ ei) {
    long long stride = (long long)gridDim.x * blockDim.x;
    bool is64 = (g_orflag == 0u);
    for (long long e = (long long)blockIdx.x * blockDim.x + threadIdx.x; e < NE; e += stride) {
        int s, d;
        if (is64) {
            s = (int)((const long long*)ei)[e];
            d = (int)((const long long*)ei)[NE + e];
        } else {
            s = ((const int*)ei)[e];
            d = ((const int*)ei)[NE + e];
        }
        if ((unsigned)s >= (unsigned)NN || (unsigned)d >= (unsigned)NN) continue;
        int pos = atomicAdd(&g_cursor[d], 1);
        g_csr_src[pos] = s;
    }
}

// ---------------- pull: warp per node, 2 edges/iter, 16 lanes x uint4 per edge ----
// acc = Sum_{s in in(d)} P[s] + P[d];  r = dinv[d] * acc
// LAYER==1: reads g_P0, writes g_P1 = fp16(dinv * relu(r + b1)).
// LAYER==2: reads g_P1, writes g_aggh = fp16(r).
template <int LAYER>
__global__ void pull_kernel(const float* __restrict__ b1) {
    long long gt = (long long)blockIdx.x * blockDim.x + threadIdx.x;
    int n = (int)(gt >> 5);
    int lane = (int)(gt & 31);
    if (n >= NN) return;
    const __half* H = (LAYER == 1) ? g_P0 : g_P1;
    int g = lane >> 4;       // edge-slot 0/1
    int l = lane & 15;       // channel group: halves l*8 .. l*8+7
    int row = g_rowstart[n];
    int end = g_rowstart[n + 1];
    float acc[8];
    #pragma unroll
    for (int i = 0; i < 8; i++) acc[i] = 0.f;

    for (int e = row + g; e < end; e += 2) {
        int s = g_csr_src[e];
        uint4 raw = *(const uint4*)(H + (size_t)s * CH + l * 8);
        float2 f0 = __half22float2(*reinterpret_cast<__half2*>(&raw.x));
        float2 f1 = __half22float2(*reinterpret_cast<__half2*>(&raw.y));
        float2 f2 = __half22float2(*reinterpret_cast<__half2*>(&raw.z));
        float2 f3 = __half22float2(*reinterpret_cast<__half2*>(&raw.w));
        acc[0] += f0.x; acc[1] += f0.y; acc[2] += f1.x; acc[3] += f1.y;
        acc[4] += f2.x; acc[5] += f2.y; acc[6] += f3.x; acc[7] += f3.y;
    }
    // combine the two edge-slots
    #pragma unroll
    for (int i = 0; i < 8; i++)
        acc[i] += __shfl_xor_sync(0xffffffffu, acc[i], 16);

    if (g == 0) {
        // self-loop + scale + epilogue; lanes 0..15 write 16B each
        uint4 rawd = *(const uint4*)(H + (size_t)n * CH + l * 8);
        float2 s0 = __half22float2(*reinterpret_cast<__half2*>(&rawd.x));
        float2 s1 = __half22float2(*reinterpret_cast<__half2*>(&rawd.y));
        float2 s2 = __half22float2(*reinterpret_cast<__half2*>(&rawd.z));
        float2 s3 = __half22float2(*reinterpret_cast<__half2*>(&rawd.w));
        acc[0] += s0.x; acc[1] += s0.y; acc[2] += s1.x; acc[3] += s1.y;
        acc[4] += s2.x; acc[5] += s2.y; acc[6] += s3.x; acc[7] += s3.y;
        float dd = g_dinv[n];
        float r[8];
        #pragma unroll
        for (int i = 0; i < 8; i++) r[i] = dd * acc[i];
        if (LAYER == 1) {
            float4 ba = ((const float4*)b1)[l * 2];
            float4 bb = ((const float4*)b1)[l * 2 + 1];
            r[0] = dd * fmaxf(r[0] + ba.x, 0.f);
            r[1] = dd * fmaxf(r[1] + ba.y, 0.f);
            r[2] = dd * fmaxf(r[2] + ba.z, 0.f);
            r[3] = dd * fmaxf(r[3] + ba.w, 0.f);
            r[4] = dd * fmaxf(r[4] + bb.x, 0.f);
            r[5] = dd * fmaxf(r[5] + bb.y, 0.f);
            r[6] = dd * fmaxf(r[6] + bb.z, 0.f);
            r[7] = dd * fmaxf(r[7] + bb.w, 0.f);
        }
        uint4 outp;
        *reinterpret_cast<__half2*>(&outp.x) = __floats2half2_rn(r[0], r[1]);
        *reinterpret_cast<__half2*>(&outp.y) = __floats2half2_rn(r[2], r[3]);
        *reinterpret_cast<__half2*>(&outp.z) = __floats2half2_rn(r[4], r[5]);
        *reinterpret_cast<__half2*>(&outp.w) = __floats2half2_rn(r[6], r[7]);
        __half* dst = (LAYER == 1) ? g_P1 : g_aggh;
        *(uint4*)(dst + (size_t)n * CH + l * 8) = outp;
    }
}

// ---------------- shared HMMA core pieces ----------------
__device__ __forceinline__ void hmma_compute(const __half* As, const __half* Bt,
                                             int wbase, int gid, int tig,
                                             float c[16][4]) {
    #pragma unroll
    for (int n = 0; n < 16; n++)
        c[n][0] = c[n][1] = c[n][2] = c[n][3] = 0.f;
    #pragma unroll
    for (int k = 0; k < 8; k++) {
        int k16 = k * 16;
        unsigned a0 = *(const unsigned*)(As + (wbase + gid) * SPAD + k16 + tig * 2);
        unsigned a1 = *(const unsigned*)(As + (wbase + gid + 8) * SPAD + k16 + tig * 2);
        unsigned a2 = *(const unsigned*)(As + (wbase + gid) * SPAD + k16 + 8 + tig * 2);
        unsigned a3 = *(const unsigned*)(As + (wbase + gid + 8) * SPAD + k16 + 8 + tig * 2);
        #pragma unroll
        for (int n = 0; n < 16; n++) {
            unsigned b0 = *(const unsigned*)(Bt + (n * 8 + gid) * SPAD + k16 + tig * 2);
            unsigned b1 = *(const unsigned*)(Bt + (n * 8 + gid) * SPAD + k16 + 8 + tig * 2);
            asm volatile(
                "mma.sync.aligned.m16n8k16.row.col.f32.f16.f16.f32 "
                "{%0,%1,%2,%3}, {%4,%5,%6,%7}, {%8,%9}, {%0,%1,%2,%3};\n"
                : "+f"(c[n][0]), "+f"(c[n][1]), "+f"(c[n][2]), "+f"(c[n][3])
                : "r"(a0), "r"(a1), "r"(a2), "r"(a3), "r"(b0), "r"(b1));
        }
    }
}

// ---------------- GEMM layer 1: g_P0 = fp16(dinv * (x @ W1)) ----------------
__global__ __launch_bounds__(256) void hgemm1_kernel(const float* __restrict__ Af,
                                                     const float* __restrict__ Bf) {
    extern __shared__ __half sm[];
    __half* As = sm;
    __half* Bt = sm + 128 * SPAD;
    int tid = threadIdx.x;
    long long rowBase = (long long)blockIdx.x * 128;

    for (int idx = tid; idx < 128 * 32; idx += 256) {
        int row = idx >> 5, c4 = (idx & 31) * 4;
        long long gr = rowBase + row;
        float4 v = make_float4(0.f, 0.f, 0.f, 0.f);
        if (gr < NN) v = *(const float4*)(Af + (size_t)gr * 128 + c4);
        __half* p = As + row * SPAD + c4;
        p[0] = __float2half_rn(v.x); p[1] = __float2half_rn(v.y);
        p[2] = __float2half_rn(v.z); p[3] = __float2half_rn(v.w);
    }
    for (int idx = tid; idx < 128 * 32; idx += 256) {
        int k = idx >> 5, n4 = (idx & 31) * 4;
        float4 v = *(const float4*)(Bf + (size_t)k * 128 + n4);
        Bt[(n4 + 0) * SPAD + k] = __float2half_rn(v.x);
        Bt[(n4 + 1) * SPAD + k] = __float2half_rn(v.y);
        Bt[(n4 + 2) * SPAD + k] = __float2half_rn(v.z);
        Bt[(n4 + 3) * SPAD + k] = __float2half_rn(v.w);
    }
    __syncthreads();

    int w = tid >> 5, lane = tid & 31;
    int gid = lane >> 2, tig = lane & 3;
    int wbase = w * 16;
    float c[16][4];
    hmma_compute(As, Bt, wbase, gid, tig, c);

    long long r0 = rowBase + wbase + gid;
    long long r1 = r0 + 8;
    float d0 = (r0 < NN) ? g_dinv[r0] : 0.f;
    float d1 = (r1 < NN) ? g_dinv[r1] : 0.f;
    #pragma unroll
    for (int n = 0; n < 16; n++) {
        int col = n * 8 + tig * 2;
        if (r0 < NN)
            *(__half2*)(g_P0 + (size_t)r0 * 128 + col) = __floats2half2_rn(d0 * c[n][0], d0 * c[n][1]);
        if (r1 < NN)
            *(__half2*)(g_P0 + (size_t)r1 * 128 + col) = __floats2half2_rn(d1 * c[n][2], d1 * c[n][3]);
    }
}

// ---------------- GEMM layer 2: out = g_aggh @ [W_mu|W_ls] + [b_mu|b_ls] ----------------
// B + bias staged directly from raw fp32 harness pointers (pack kernel eliminated).
__global__ __launch_bounds__(256) void hgemm2_kernel(const float* __restrict__ Wmu,
                                                     const float* __restrict__ Wls,
                                                     const float* __restrict__ bmu,
                                                     const float* __restrict__ bls,
                                                     float* __restrict__ Cout) {
    extern __shared__ __half sm[];
    __half* As = sm;
    __half* Bt = sm + 128 * SPAD;
    int tid = threadIdx.x;
    long long rowBase = (long long)blockIdx.x * 128;

    for (int idx = tid; idx < 128 * 16; idx += 256) {
        int row = idx >> 4, c8 = (idx & 15) * 8;
        long long gr = rowBase + row;
        uint4 v = make_uint4(0u, 0u, 0u, 0u);
        if (gr < NN) v = *(const uint4*)(g_aggh + (size_t)gr * 128 + c8);
        *(uint4*)(As + row * SPAD + c8) = v;
    }
    for (int idx = tid; idx < 128 * 32; idx += 256) {
        int k = idx >> 5, n4 = (idx & 31) * 4;    // n4 multiple of 4; never straddles 64
        float4 v = (n4 < OC) ? *(const float4*)(Wmu + (size_t)k * OC + n4)
                             : *(const float4*)(Wls + (size_t)k * OC + n4 - OC);
        Bt[(n4 + 0) * SPAD + k] = __float2half_rn(v.x);
        Bt[(n4 + 1) * SPAD + k] = __float2half_rn(v.y);
        Bt[(n4 + 2) * SPAD + k] = __float2half_rn(v.z);
        Bt[(n4 + 3) * SPAD + k] = __float2half_rn(v.w);
    }
    __syncthreads();

    int w = tid >> 5, lane = tid & 31;
    int gid = lane >> 2, tig = lane & 3;
    int wbase = w * 16;
    float c[16][4];
    hmma_compute(As, Bt, wbase, gid, tig, c);

    long long r0 = rowBase + wbase + gid;
    long long r1 = r0 + 8;
    #pragma unroll
    for (int n = 0; n < 16; n++) {
        int col = n * 8 + tig * 2;                // col, col+1 same side of 64
        float bb0, bb1;
        float* base;
        int cc;
        if (col < OC) { base = Cout;            cc = col;      bb0 = bmu[col];      bb1 = bmu[col + 1]; }
        else          { base = Cout + HALF_OFF; cc = col - OC; bb0 = bls[col - OC]; bb1 = bls[col - OC + 1]; }
        if (r0 < NN)
            *(float2*)(base + (size_t)r0 * OC + cc) = make_float2(c[n][0] + bb0, c[n][1] + bb1);
        if (r1 < NN)
            *(float2*)(base + (size_t)r1 * OC + cc) = make_float2(c[n][2] + bb0, c[n][3] + bb1);
    }
}

// ---------------- launch ----------------
extern "C" void kernel_launch(void* const* d_in, const int* in_sizes, int n_in,
                              void* d_out, int out_size) {
    const float *x = 0, *W1 = 0, *b1 = 0, *Wmu = 0, *Wls = 0, *bmu = 0, *bls = 0;
    const void *ei = 0;
    for (int i = 0; i < n_in; i++) {
        long long s = in_sizes[i];
        if (s == 12800000LL)                        x  = (const float*)d_in[i];
        else if (s == 3200000LL || s == 6400000LL)  ei = d_in[i];
        else if (s == 16384LL)                      W1 = (const float*)d_in[i];
        else if (s == 128LL)                        b1 = (const float*)d_in[i];
        else if (s == 8192LL) { if (!Wmu) Wmu = (const float*)d_in[i]; else Wls = (const float*)d_in[i]; }
        else if (s == 64LL)   { if (!bmu) bmu = (const float*)d_in[i]; else bls = (const float*)d_in[i]; }
    }
    float* out = (float*)d_out;
    if (!x || !ei || !W1 || !b1 || !Wmu || !Wls || !bmu || !bls) return;  // Signal A
    if (!((long long)out_size == OUT_ELEMS || (long long)out_size == 4 * OUT_ELEMS)) {
        crash_kernel<<<1, 1>>>();  // Signal B
        return;
    }

    const int T = 256;
    int gemmBlocks = (NN + 127) / 128;       // 782
    int pullBlocks = (NN * 32 + T - 1) / T;  // 12500
    int smemBytes = 2 * 128 * SPAD * 2;      // 69632

    cudaFuncSetAttribute(hgemm1_kernel, cudaFuncAttributeMaxDynamicSharedMemorySize, smemBytes);
    cudaFuncSetAttribute(hgemm2_kernel, cudaFuncAttributeMaxDynamicSharedMemorySize, smemBytes);

    // edges + degrees + CSR (9 launches total)
    initdetect_kernel<<<400, T>>>((const unsigned int*)ei);
    hist_kernel<<<4096, T>>>(ei);
    scan1_kernel<<<SCAN_BLK, T>>>();        // also computes dinv
    scan23_kernel<<<SCAN_BLK, T>>>();
    fill_kernel<<<4096, T>>>(ei);

    // layer 1: g_P0 = fp16(dinv * (x @ W1)) ; g_P1 = fp16(dinv * relu(pull + b1))
    hgemm1_kernel<<<gemmBlocks, T, smemBytes>>>(x, W1);
    pull_kernel<1><<<pullBlocks, T>>>(b1);

    // layer 2: g_aggh = fp16(pull(g_P1)) ; out = g_aggh @ [W_mu|W_ls] + bias
    pull_kernel<2><<<pullBlocks, T>>>(nullptr);
    hgemm2_kernel<<<gemmBlocks, T, smemBytes>>>(Wmu, Wls, bmu, bls, out);
}